// round 12
// baseline (speedup 1.0000x reference)
#include <cuda_runtime.h>
#include <stdint.h>

#define BATCH   64
#define NA      3234
#define NC      91
#define CM1     90
#define CAP     512
#define KMAX    200
#define WMAX    7
#define POOLCAP 16384

typedef unsigned long long u64;
typedef unsigned int u32;
#define FULL 0xffffffffu

// -------- scratch (static __device__ — zero-init at load; re-zeroed by k_top) ----
__device__ float4 g_boxes[BATCH * NA];
__device__ u64    g_cand[(size_t)BATCH * CM1 * CAP];
__device__ int    g_candCnt[BATCH * CM1];
__device__ u64    g_pool[(size_t)BATCH * POOLCAP];
__device__ int    g_poolCnt[BATCH];
__device__ int    g_bigCnt;
__device__ int    g_bigList[BATCH * CM1];
__device__ int    g_doneCnt;

// ~1-ulp exp, FMA-only (immune to fast-math substitution).
__device__ __forceinline__ float exp_acc(float x) {
    float k = rintf(x * 1.44269504088896340736f);
    float r = fmaf(k, -0.693359375f, x);
    r = fmaf(k, 2.12194440054690582762e-4f, r);
    float p = 1.98412698412698413e-4f;
    p = fmaf(p, r, 1.38888888888888889e-3f);
    p = fmaf(p, r, 8.33333333333333333e-3f);
    p = fmaf(p, r, 4.16666666666666667e-2f);
    p = fmaf(p, r, 1.66666666666666667e-1f);
    p = fmaf(p, r, 0.5f);
    p = fmaf(p, r, 1.0f);
    p = fmaf(p, r, 1.0f);
    int ki = (int)k;
    ki = max(-126, min(126, ki));
    return p * __int_as_float((ki + 127) << 23);
}

__device__ __forceinline__ u32 f2ord(float x) {
    u32 u = __float_as_uint(x);
    return (u & 0x80000000u) ? ~u : (u | 0x80000000u);
}
__device__ __forceinline__ float ord2f(u32 k) {
    u32 u = (k & 0x80000000u) ? (k ^ 0x80000000u) : ~k;
    return __uint_as_float(u);
}

// ---- packed f32x2 helpers (sm_103a) ----
#define MUL2(d, a, b)    asm("mul.rn.f32x2 %0, %1, %2;" : "=l"(d) : "l"(a), "l"(b))
#define ADD2(d, a, b)    asm("add.rn.f32x2 %0, %1, %2;" : "=l"(d) : "l"(a), "l"(b))
#define FMA2(d, a, b, c) asm("fma.rn.f32x2 %0, %1, %2, %3;" : "=l"(d) : "l"(a), "l"(b), "l"(c))

__device__ __forceinline__ u64 pk2(float lo, float hi) {
    u64 r; asm("mov.b64 %0, {%1, %2};" : "=l"(r) : "f"(lo), "f"(hi)); return r;
}
__device__ __forceinline__ void upk2(u64 v, float& lo, float& hi) {
    asm("mov.b64 {%0, %1}, %2;" : "=f"(lo), "=f"(hi) : "l"(v));
}
__device__ __forceinline__ u64 dupc(float f) {
    u32 u = __float_as_uint(f);
    return ((u64)u << 32) | (u64)u;
}

// packed dual exp — per-half bit-identical to exp_acc:
// rint via magic add (RN ties-even == rintf); integer k read from float bits.
__device__ __forceinline__ u64 exp_acc2(u64 x2) {
    u64 t, km, k2, r, p;
    MUL2(t, x2, dupc(1.44269504088896340736f));
    ADD2(km, t, dupc(12582912.0f));            // 1.5*2^23: km = magic + rint(t)
    ADD2(k2, km, dupc(-12582912.0f));          // k = rint(t), exact
    FMA2(r, k2, dupc(-0.693359375f), x2);
    FMA2(r, k2, dupc(2.12194440054690582762e-4f), r);
    p = dupc(1.98412698412698413e-4f);
    FMA2(p, p, r, dupc(1.38888888888888889e-3f));
    FMA2(p, p, r, dupc(8.33333333333333333e-3f));
    FMA2(p, p, r, dupc(4.16666666666666667e-2f));
    FMA2(p, p, r, dupc(1.66666666666666667e-1f));
    FMA2(p, p, r, dupc(0.5f));
    FMA2(p, p, r, dupc(1.0f));
    FMA2(p, p, r, dupc(1.0f));
    int kia = (int)((u32)km - 0x4B400000u);    // integer k, low half
    int kib = (int)((u32)(km >> 32) - 0x4B400000u);
    kia = max(-126, min(126, kia));
    kib = max(-126, min(126, kib));
    u64 sc = ((u64)((u32)(kib + 127) << 23) << 32) | (u32)((kia + 127) << 23);
    u64 out;
    MUL2(out, p, sc);
    return out;
}

// warp-collective descending bitonic sort, R u64 keys per lane (N = 32*R).
template <int R>
__device__ __forceinline__ void warp_bitonic_desc(u64 key[4], int lane) {
    const int N = R * 32;
#pragma unroll
    for (int k = 2; k <= N; k <<= 1) {
#pragma unroll
        for (int j = k >> 1; j > 0; j >>= 1) {
            if (j >= 32) {
                int rj = j >> 5;
#pragma unroll
                for (int r = 0; r < R; r++) {
                    if ((r & rj) == 0) {
                        int rp = r | rj;
                        int e = r * 32 + lane;
                        bool desc = ((e & k) == 0);
                        u64 A = key[r], Bv = key[rp];
                        if (desc ? (A < Bv) : (A > Bv)) { key[r] = Bv; key[rp] = A; }
                    }
                }
            } else {
#pragma unroll
                for (int r = 0; r < R; r++) {
                    u64 other = __shfl_xor_sync(FULL, key[r], j);
                    int e = r * 32 + lane;
                    bool desc = ((e & k) == 0);
                    bool lower = ((lane & j) == 0);
                    if (desc == lower) key[r] = (key[r] > other) ? key[r] : other;
                    else               key[r] = (key[r] < other) ? key[r] : other;
                }
            }
        }
    }
}

// -------- kernel 1: fused decode + dual-anchor softmax + threshold filter ------
__device__ __forceinline__ void push_cand2(float e, int cm1, bool cvalid,
                                           int b, int a, float s, float pre) {
    if (cvalid && e > pre) {
        float p = __fdiv_rn(e, s);
        if (p > 0.05f) {
            int li = b * CM1 + cm1;
            int pos = atomicAdd(&g_candCnt[li], 1);
            if (pos < CAP)
                g_cand[(size_t)li * CAP + pos] =
                    ((u64)__float_as_uint(p) << 32) | (u32)(~(u32)a);
        }
    }
}

__global__ void __launch_bounds__(512) k_cand(const float* __restrict__ logits,
                                              const float* __restrict__ box_reg,
                                              const float* __restrict__ priors) {
    // decode prologue: one thread per (b,a)
    int di = blockIdx.x * 512 + threadIdx.x;
    if (di < BATCH * NA) {
        int da = di % NA;
        float4 loc = ((const float4*)box_reg)[di];
        float4 pr  = ((const float4*)priors)[da];
        float pw = pr.z - pr.x, ph = pr.w - pr.y;
        float cx = pr.x + 0.5f * pw, cy = pr.y + 0.5f * ph;
        float x = loc.x * 0.1f * pw + cx;
        float y = loc.y * 0.1f * ph + cy;
        float w = exp_acc(loc.z * 0.2f) * pw;
        float h = exp_acc(loc.w * 0.2f) * ph;
        g_boxes[di] = make_float4(x - w * 0.5f, y - h * 0.5f, x + w * 0.5f, y + h * 0.5f);
    }

    // two anchors per warp, fully interleaved
    int gw = di >> 5;
    int lane = threadIdx.x & 31;
    int idx0 = gw * 2;
    int idx1 = idx0 + 1;
    if (idx0 >= BATCH * NA) return;
    int b0 = idx0 / NA, a0 = idx0 - b0 * NA;
    int b1 = b0, a1 = a0 + 1;
    if (a1 == NA) { b1 = b0 + 1; a1 = 0; }
    const float* LA = logits + (size_t)idx0 * NC;
    const float* LB = logits + (size_t)idx1 * NC;
    bool t2 = lane < NC - 64;

    float al0 = LA[lane];
    float al1 = LA[lane + 32];
    float al2 = t2 ? LA[lane + 64] : -1e30f;
    float bl0 = LB[lane];
    float bl1 = LB[lane + 32];
    float bl2 = t2 ? LB[lane + 64] : -1e30f;

    u32 oma = max(f2ord(al0), max(f2ord(al1), f2ord(al2)));
    u32 omb = max(f2ord(bl0), max(f2ord(bl1), f2ord(bl2)));
    float mxa = ord2f(__reduce_max_sync(FULL, oma));
    float mxb = ord2f(__reduce_max_sync(FULL, omb));

    // packed exps: lo half = anchor0, hi half = anchor1 (bit-identical per half)
    u64 x0 = pk2(al0 - mxa, bl0 - mxb);
    u64 x1 = pk2(al1 - mxa, bl1 - mxb);
    u64 xv2 = pk2(al2 - mxa, bl2 - mxb);
    u64 e0p = exp_acc2(x0);
    u64 e1p = exp_acc2(x1);
    u64 e2p = t2 ? exp_acc2(xv2) : 0ULL;

    // packed sum (same left association per half as scalar)
    u64 pk;
    ADD2(pk, e0p, e1p);
    ADD2(pk, pk, e2p);
#pragma unroll
    for (int o = 16; o; o >>= 1) {
        u64 other = __shfl_xor_sync(FULL, pk, o);
        ADD2(pk, pk, other);
    }
    float sa, sb;
    upk2(pk, sa, sb);

    float ea0, eb0, ea1, eb1, ea2, eb2;
    upk2(e0p, ea0, eb0);
    upk2(e1p, ea1, eb1);
    upk2(e2p, ea2, eb2);

    float prea = 0.0495f * sa;
    float preb = 0.0495f * sb;
    bool l0v = lane > 0;
    push_cand2(ea0, lane - 1,  l0v,  b0, a0, sa, prea);
    push_cand2(eb0, lane - 1,  l0v,  b1, a1, sb, preb);
    push_cand2(ea1, lane + 31, true, b0, a0, sa, prea);
    push_cand2(eb1, lane + 31, true, b1, a1, sb, preb);
    push_cand2(ea2, lane + 63, true, b0, a0, sa, prea);
    push_cand2(eb2, lane + 63, true, b1, a1, sb, preb);
}

// -------- kernel 2: warp-per-class NMS (shared masks, lane-0 scan) --------
__global__ void __launch_bounds__(128) k_nms_warp() {
    __shared__ float4 sbox[4][128];
    __shared__ float  sarea[4][128];
    __shared__ u32    smask[4][128 * 4];

    int wid = threadIdx.x >> 5;
    int lane = threadIdx.x & 31;
    int li = blockIdx.x * 4 + wid;
    if (li >= BATCH * CM1) return;
    int b = li / CM1;
    int c = li - b * CM1;

    int m = g_candCnt[li];
    if (m == 0) return;
    if (m > 128) {                         // rare fallback, handled in k_top
        if (lane == 0) {
            int p = atomicAdd(&g_bigCnt, 1);
            g_bigList[p] = li;
        }
        return;
    }

    u64 key[4];
#pragma unroll
    for (int r = 0; r < 4; r++) {
        int e = r * 32 + lane;
        key[r] = (e < m) ? g_cand[(size_t)li * CAP + e] : 0ULL;
    }

    if (m <= 64) warp_bitonic_desc<2>(key, lane);   // 21 stages, 2 keys/lane
    else         warp_bitonic_desc<4>(key, lane);   // 28 stages, 4 keys/lane

    int K = m;   // <= 128 <= KMAX

#pragma unroll
    for (int r = 0; r < 4; r++) {
        int e = r * 32 + lane;
        if (e < K) {
            int a = (int)(~(u32)key[r]);
            float4 bb = g_boxes[b * NA + a];
            sbox[wid][e] = bb;
            sarea[wid][e] = fmaxf(bb.z - bb.x, 0.f) * fmaxf(bb.w - bb.y, 0.f);
        }
    }
    __syncwarp();

    // suppression rows: load-balanced row map {lane, 63-lane, 64+lane, 127-lane}
    int lastseg = (K - 1) >> 5;
#pragma unroll
    for (int rr = 0; rr < 4; rr++) {
        int i;
        if (rr == 0)      i = lane;
        else if (rr == 1) i = 63 - lane;
        else if (rr == 2) i = 64 + lane;
        else              i = 127 - lane;
        if (i < K) {
            float4 bi = sbox[wid][i];
            float ai = sarea[wid][i];
#pragma unroll
            for (int seg = 0; seg < 4; seg++) {
                u32 bits = 0;
                if (seg <= lastseg) {
                    int j0 = seg << 5; if (j0 < i + 1) j0 = i + 1;
                    int je = (seg << 5) + 32; if (je > K) je = K;
                    for (int j = j0; j < je; j++) {
                        float4 bj = sbox[wid][j];
                        float iw = fminf(bi.z, bj.z) - fmaxf(bi.x, bj.x);
                        float ih = fminf(bi.w, bj.w) - fmaxf(bi.y, bj.y);
                        iw = fmaxf(iw, 0.f); ih = fmaxf(ih, 0.f);
                        float inter = iw * ih;
                        float sum = ai + sarea[wid][j];
                        if (inter > 0.332f * sum) {      // superset prefilter
                            float uni = sum - inter;
                            if (__fdiv_rn(inter, fmaxf(uni, 1e-9f)) > 0.5f)
                                bits |= 1u << (j & 31);
                        }
                    }
                }
                smask[wid][i * 4 + seg] = bits;
            }
        }
    }
    __syncwarp();

    u32 kw0 = 0, kw1 = 0, kw2 = 0, kw3 = 0;
    int base = 0;
    if (lane == 0) {
        u32 rem[4];
#pragma unroll
        for (int w = 0; w < 4; w++) {
            int lo = w * 32;
            rem[w] = (K >= lo + 32) ? 0xffffffffu : (K > lo ? ((1u << (K - lo)) - 1u) : 0u);
        }
        u32 kw[4] = {0, 0, 0, 0};
#pragma unroll
        for (int w = 0; w < 4; w++) {
            while (rem[w]) {
                int bit = __ffs(rem[w]) - 1;
                int i = w * 32 + bit;
                kw[w] |= 1u << bit;
                rem[w] &= ~(1u << bit);
                uint4 row = *(const uint4*)&smask[wid][i * 4];
                rem[0] &= ~row.x; rem[1] &= ~row.y;
                rem[2] &= ~row.z; rem[3] &= ~row.w;
            }
        }
        int nkeep = __popc(kw[0]) + __popc(kw[1]) + __popc(kw[2]) + __popc(kw[3]);
        base = atomicAdd(&g_poolCnt[b], nkeep);
        kw0 = kw[0]; kw1 = kw[1]; kw2 = kw[2]; kw3 = kw[3];
    }
    kw0 = __shfl_sync(FULL, kw0, 0);
    kw1 = __shfl_sync(FULL, kw1, 0);
    kw2 = __shfl_sync(FULL, kw2, 0);
    kw3 = __shfl_sync(FULL, kw3, 0);
    base = __shfl_sync(FULL, base, 0);

    int pre1 = __popc(kw0);
    int pre2 = pre1 + __popc(kw1);
    int pre3 = pre2 + __popc(kw2);
#pragma unroll
    for (int r = 0; r < 4; r++) {
        int e = r * 32 + lane;
        u32 kwr = (r == 0) ? kw0 : (r == 1) ? kw1 : (r == 2) ? kw2 : kw3;
        int prer = (r == 0) ? 0 : (r == 1) ? pre1 : (r == 2) ? pre2 : pre3;
        if (e < K && ((kwr >> lane) & 1u)) {
            int rank = prer + __popc(kwr & ((1u << lane) - 1u));
            u64 kk = key[r];
            int a = (int)(~(u32)kk) & 0xFFF;
            int flat = c * KMAX + e;
            u64 det = (kk & 0xFFFFFFFF00000000ULL)
                    | ((u64)(u32)(32767 - flat) << 17)
                    | ((u64)(u32)a << 5);
            int pos = base + rank;
            if (pos < POOLCAP) g_pool[(size_t)b * POOLCAP + pos] = det;
        }
    }
}

// score bucket: monotonic linear map of score (0,1] -> 0..4095
__device__ __forceinline__ int score_bucket(u64 kk) {
    float sc = __uint_as_float((u32)(kk >> 32));
    int d = (int)(sc * 4096.0f);
    return d > 4095 ? 4095 : d;
}

// -------- kernel 3: big-class fallback + 1-pass score-hist top-100 + re-zero ----
__global__ void __launch_bounds__(1024) k_top(float* __restrict__ out) {
    __shared__ int hist[4096];
    __shared__ int segs[256];
    __shared__ u64 sel[128];
    __shared__ int sh_cnt;
    __shared__ u64 sh_prefix;
    __shared__ int sh_rem, sh_total, sh_d;
    __shared__ u64 fkeys[CAP];
    __shared__ float4 fbox[KMAX];
    __shared__ float farea[KMAX];
    __shared__ u32 fmask[KMAX * WMAX];
    __shared__ int fkl[KMAX];
    __shared__ int f_nk, f_base;

    int b = blockIdx.x, tid = threadIdx.x;

    // ---- rare fallback: block-level NMS for this image's m>128 classes ----
    int nbig = g_bigCnt;
    for (int idx = 0; idx < nbig; idx++) {
        int li = g_bigList[idx];
        if (li / CM1 != b) continue;
        int c = li - b * CM1;
        int mm = g_candCnt[li];
        if (mm > CAP) mm = CAP;

        int n = 1; while (n < mm) n <<= 1;
        for (int i = tid; i < n; i += 1024)
            fkeys[i] = (i < mm) ? g_cand[(size_t)li * CAP + i] : 0ULL;
        __syncthreads();
        for (int k = 2; k <= n; k <<= 1)
            for (int j = k >> 1; j > 0; j >>= 1) {
                for (int i = tid; i < n; i += 1024) {
                    int x = i ^ j;
                    if (x > i) {
                        u64 A = fkeys[i], Bv = fkeys[x];
                        bool up = (i & k) == 0;
                        if (up ? (A < Bv) : (A > Bv)) { fkeys[i] = Bv; fkeys[x] = A; }
                    }
                }
                __syncthreads();
            }

        int K = mm < KMAX ? mm : KMAX;
        for (int r = tid; r < K; r += 1024) {
            int a = (int)(~(u32)fkeys[r]);
            float4 bb = g_boxes[b * NA + a];
            fbox[r] = bb;
            farea[r] = fmaxf(bb.z - bb.x, 0.f) * fmaxf(bb.w - bb.y, 0.f);
        }
        __syncthreads();

        int W = (K + 31) >> 5;
        for (int w = tid; w < K * W; w += 1024) {
            int i = w / W, seg = w - i * W;
            u32 bits = 0;
            float4 bi = fbox[i];
            float ai = farea[i];
            int j0 = seg << 5;
            int je = min(j0 + 32, K);
            for (int j = max(j0, i + 1); j < je; j++) {
                float4 bj = fbox[j];
                float iw = fminf(bi.z, bj.z) - fmaxf(bi.x, bj.x);
                float ih = fminf(bi.w, bj.w) - fmaxf(bi.y, bj.y);
                iw = fmaxf(iw, 0.f); ih = fmaxf(ih, 0.f);
                float inter = iw * ih;
                float uni = ai + farea[j] - inter;
                if (inter > 0.4985f * uni)
                    if (__fdiv_rn(inter, fmaxf(uni, 1e-9f)) > 0.5f)
                        bits |= 1u << (j - j0);
            }
            fmask[i * W + seg] = bits;
        }
        __syncthreads();

        if (tid == 0) {
            u32 remv[WMAX] = {0, 0, 0, 0, 0, 0, 0};
            int nkeep = 0;
            for (int i = 0; i < K; i++) {
                if (!((remv[i >> 5] >> (i & 31)) & 1u)) {
                    fkl[nkeep++] = i;
                    for (int w = 0; w < W; w++) remv[w] |= fmask[i * W + w];
                }
            }
            f_nk = nkeep;
            f_base = atomicAdd(&g_poolCnt[b], nkeep);
        }
        __syncthreads();

        int nk = f_nk, bse = f_base;
        for (int sidx = tid; sidx < nk; sidx += 1024) {
            int i = fkl[sidx];
            u64 kk = fkeys[i];
            int a = (int)(~(u32)kk) & 0xFFF;
            int flat = c * KMAX + i;
            u64 det = (kk & 0xFFFFFFFF00000000ULL)
                    | ((u64)(u32)(32767 - flat) << 17)
                    | ((u64)(u32)a << 5);
            int pos = bse + sidx;
            if (pos < POOLCAP) g_pool[(size_t)b * POOLCAP + pos] = det;
        }
        __syncthreads();
    }

    // ---- selection: 1-pass linear-score histogram (fallback: exact u64 radix) ----
    int m = g_poolCnt[b]; if (m > POOLCAP) m = POOLCAP;
    const u64* pool = g_pool + (size_t)b * POOLCAP;

    u64 kth = 0;        // used by fallback path
    int dstar = -1;     // used by fast path (bucket threshold)
    if (m > 100) {
        // fast path: histogram over score buckets
        for (int d = tid; d < 4096; d += 1024) hist[d] = 0;
        __syncthreads();
        for (int i = tid; i < m; i += 1024)
            atomicAdd(&hist[score_bucket(pool[i])], 1);
        __syncthreads();
        if (tid < 256) {
            int s = 0;
#pragma unroll
            for (int q = 0; q < 16; q++) s += hist[tid * 16 + q];
            segs[tid] = s;
        }
        __syncthreads();
        if (tid < 32) {
            int sv[8]; int lsum = 0;
#pragma unroll
            for (int q = 0; q < 8; q++) { sv[q] = segs[tid * 8 + q]; lsum += sv[q]; }
            int acc = lsum;
#pragma unroll
            for (int off = 1; off < 32; off <<= 1) {
                int v = __shfl_down_sync(FULL, acc, off);
                if (tid + off < 32) acc += v;
            }
            int run = acc - lsum;
#pragma unroll
            for (int q = 7; q >= 0; q--) { run += sv[q]; segs[tid * 8 + q] = run; }
        }
        __syncthreads();
        if (tid < 256) {
            int run = (tid < 255) ? segs[tid + 1] : 0;
#pragma unroll
            for (int q = 15; q >= 0; q--) {
                int d = tid * 16 + q;
                int ge = run + hist[d];
                if (ge >= 100 && run < 100) {
                    sh_d = d;
                    sh_total = ge;
                }
                run = ge;
            }
        }
        __syncthreads();
        if (sh_total <= 128) {
            dstar = sh_d;                       // 1-pass success (typical)
        } else {
            // exact 4-pass u64 radix fallback (rare: >28 keys in one bucket at rank 100)
            u64 prefix = 0; int rem = 100;
            for (int pass = 0; pass < 4; pass++) {
                int shift = 52 - 12 * pass;
                for (int d = tid; d < 4096; d += 1024) hist[d] = 0;
                __syncthreads();
                for (int i = tid; i < m; i += 1024) {
                    u64 kk = pool[i];
                    if (pass == 0 || (kk >> (shift + 12)) == prefix)
                        atomicAdd(&hist[(int)((kk >> shift) & 0xFFF)], 1);
                }
                __syncthreads();
                if (tid < 256) {
                    int s = 0;
#pragma unroll
                    for (int q = 0; q < 16; q++) s += hist[tid * 16 + q];
                    segs[tid] = s;
                }
                __syncthreads();
                if (tid < 32) {
                    int sv[8]; int lsum = 0;
#pragma unroll
                    for (int q = 0; q < 8; q++) { sv[q] = segs[tid * 8 + q]; lsum += sv[q]; }
                    int acc = lsum;
#pragma unroll
                    for (int off = 1; off < 32; off <<= 1) {
                        int v = __shfl_down_sync(FULL, acc, off);
                        if (tid + off < 32) acc += v;
                    }
                    int run = acc - lsum;
#pragma unroll
                    for (int q = 7; q >= 0; q--) { run += sv[q]; segs[tid * 8 + q] = run; }
                }
                __syncthreads();
                if (tid < 256) {
                    int run = (tid < 255) ? segs[tid + 1] : 0;
#pragma unroll
                    for (int q = 15; q >= 0; q--) {
                        int d = tid * 16 + q;
                        int ge = run + hist[d];
                        if (ge >= rem && run < rem) {
                            sh_prefix = (prefix << 12) | (u64)d;
                            sh_rem = rem - run;
                            sh_total = (100 - rem) + ge;
                        }
                        run = ge;
                    }
                }
                __syncthreads();
                prefix = sh_prefix; rem = sh_rem;
                int total = sh_total;
                __syncthreads();
                kth = prefix << shift;
                if (total <= 128) break;
            }
        }
    }

    if (tid == 0) sh_cnt = 0;
    __syncthreads();
    for (int i = tid; i < m; i += 1024) {
        u64 kk = pool[i];
        bool take = (dstar >= 0) ? (score_bucket(kk) >= dstar) : (kk >= kth);
        if (take) {
            int p = atomicAdd(&sh_cnt, 1);
            if (p < 128) sel[p] = kk;
        }
    }
    __syncthreads();
    int cnt = sh_cnt; if (cnt > 128) cnt = 128;
    int nsel = cnt < 100 ? cnt : 100;
    if (tid < 128 && tid >= cnt) sel[tid] = 0;
    __syncthreads();

    if (tid < 32) {
        u64 kk[4];
#pragma unroll
        for (int r = 0; r < 4; r++) kk[r] = sel[r * 32 + tid];
        warp_bitonic_desc<4>(kk, tid);
#pragma unroll
        for (int r = 0; r < 4; r++) sel[r * 32 + tid] = kk[r];
    }
    __syncthreads();

    for (int r = tid; r < 100; r += 1024) {
        float o0 = 0, o1 = 0, o2 = 0, o3 = 0, o4 = 0, o5 = 0;
        if (r < nsel) {
            u64 kk = sel[r];
            float sc = __uint_as_float((u32)(kk >> 32));
            int flat = 32767 - (int)((kk >> 17) & 0x7FFF);
            int cls = flat / 200 + 1;
            int a = (int)((kk >> 5) & 0xFFF);
            float4 bb = g_boxes[b * NA + a];
            o0 = bb.x; o1 = bb.y; o2 = bb.z; o3 = bb.w; o4 = sc; o5 = (float)cls;
        }
        float* op = out + ((size_t)b * 100 + r) * 6;
        op[0] = o0; op[1] = o1; op[2] = o2; op[3] = o3; op[4] = o4; op[5] = o5;
    }

    // ---- re-zero this image's counters for the next replay (after all use) ----
    for (int i = tid; i < CM1; i += 1024) g_candCnt[b * CM1 + i] = 0;
    __syncthreads();
    if (tid == 0) {
        g_poolCnt[b] = 0;
        __threadfence();
        int t = atomicAdd(&g_doneCnt, 1);
        if (t == BATCH - 1) { g_bigCnt = 0; g_doneCnt = 0; }
    }
}

// -------- launch --------
extern "C" void kernel_launch(void* const* d_in, const int* in_sizes, int n_in,
                              void* d_out, int out_size) {
    const float* logits = nullptr;
    const float* boxreg = nullptr;
    const float* priors = nullptr;
    for (int i = 0; i < n_in; i++) {
        if (in_sizes[i] == BATCH * NA * NC) logits = (const float*)d_in[i];
        else if (in_sizes[i] == BATCH * NA * 4) boxreg = (const float*)d_in[i];
        else if (in_sizes[i] == NA * 4) priors = (const float*)d_in[i];
    }
    float* out = (float*)d_out;

    k_cand<<<(BATCH * NA / 2 + 15) / 16, 512>>>(logits, boxreg, priors);
    k_nms_warp<<<(BATCH * CM1 + 3) / 4, 128>>>();
    k_top<<<BATCH, 1024>>>(out);
}

// round 13
// speedup vs baseline: 1.0356x; 1.0356x over previous
#include <cuda_runtime.h>
#include <stdint.h>

#define BATCH   64
#define NA      3234
#define NC      91
#define CM1     90
#define CAP     512
#define KMAX    200
#define WMAX    7
#define POOLCAP 16384

typedef unsigned long long u64;
typedef unsigned int u32;
#define FULL 0xffffffffu

// -------- scratch (static __device__ — zero-init at load; re-zeroed by k_top) ----
__device__ float4 g_boxes[BATCH * NA];
__device__ u64    g_cand[(size_t)BATCH * CM1 * CAP];
__device__ int    g_candCnt[BATCH * CM1];
__device__ u64    g_pool[(size_t)BATCH * POOLCAP];
__device__ int    g_poolCnt[BATCH];
__device__ int    g_bigCnt;
__device__ int    g_bigList[BATCH * CM1];
__device__ int    g_doneCnt;

// ~1-ulp exp, FMA-only (immune to fast-math substitution).
__device__ __forceinline__ float exp_acc(float x) {
    float k = rintf(x * 1.44269504088896340736f);
    float r = fmaf(k, -0.693359375f, x);
    r = fmaf(k, 2.12194440054690582762e-4f, r);
    float p = 1.98412698412698413e-4f;
    p = fmaf(p, r, 1.38888888888888889e-3f);
    p = fmaf(p, r, 8.33333333333333333e-3f);
    p = fmaf(p, r, 4.16666666666666667e-2f);
    p = fmaf(p, r, 1.66666666666666667e-1f);
    p = fmaf(p, r, 0.5f);
    p = fmaf(p, r, 1.0f);
    p = fmaf(p, r, 1.0f);
    int ki = (int)k;
    ki = max(-126, min(126, ki));
    return p * __int_as_float((ki + 127) << 23);
}

__device__ __forceinline__ u32 f2ord(float x) {
    u32 u = __float_as_uint(x);
    return (u & 0x80000000u) ? ~u : (u | 0x80000000u);
}
__device__ __forceinline__ float ord2f(u32 k) {
    u32 u = (k & 0x80000000u) ? (k ^ 0x80000000u) : ~k;
    return __uint_as_float(u);
}

// ---- packed f32x2 helpers (sm_103a) ----
#define MUL2(d, a, b)    asm("mul.rn.f32x2 %0, %1, %2;" : "=l"(d) : "l"(a), "l"(b))
#define ADD2(d, a, b)    asm("add.rn.f32x2 %0, %1, %2;" : "=l"(d) : "l"(a), "l"(b))
#define FMA2(d, a, b, c) asm("fma.rn.f32x2 %0, %1, %2, %3;" : "=l"(d) : "l"(a), "l"(b), "l"(c))

__device__ __forceinline__ u64 pk2(float lo, float hi) {
    u64 r; asm("mov.b64 %0, {%1, %2};" : "=l"(r) : "f"(lo), "f"(hi)); return r;
}
__device__ __forceinline__ void upk2(u64 v, float& lo, float& hi) {
    asm("mov.b64 {%0, %1}, %2;" : "=f"(lo), "=f"(hi) : "l"(v));
}
__device__ __forceinline__ u64 dupc(float f) {
    u32 u = __float_as_uint(f);
    return ((u64)u << 32) | (u64)u;
}

// packed dual exp — per-half bit-identical to exp_acc:
// rint via magic add (RN ties-even == rintf); integer k read from float bits.
__device__ __forceinline__ u64 exp_acc2(u64 x2) {
    u64 t, km, k2, r, p;
    MUL2(t, x2, dupc(1.44269504088896340736f));
    ADD2(km, t, dupc(12582912.0f));            // 1.5*2^23: km = magic + rint(t)
    ADD2(k2, km, dupc(-12582912.0f));          // k = rint(t), exact
    FMA2(r, k2, dupc(-0.693359375f), x2);
    FMA2(r, k2, dupc(2.12194440054690582762e-4f), r);
    p = dupc(1.98412698412698413e-4f);
    FMA2(p, p, r, dupc(1.38888888888888889e-3f));
    FMA2(p, p, r, dupc(8.33333333333333333e-3f));
    FMA2(p, p, r, dupc(4.16666666666666667e-2f));
    FMA2(p, p, r, dupc(1.66666666666666667e-1f));
    FMA2(p, p, r, dupc(0.5f));
    FMA2(p, p, r, dupc(1.0f));
    FMA2(p, p, r, dupc(1.0f));
    int kia = (int)((u32)km - 0x4B400000u);    // integer k, low half
    int kib = (int)((u32)(km >> 32) - 0x4B400000u);
    kia = max(-126, min(126, kia));
    kib = max(-126, min(126, kib));
    u64 sc = ((u64)((u32)(kib + 127) << 23) << 32) | (u32)((kia + 127) << 23);
    u64 out;
    MUL2(out, p, sc);
    return out;
}

// warp-collective descending bitonic sort, R u64 keys per lane (N = 32*R).
template <int R>
__device__ __forceinline__ void warp_bitonic_desc(u64 key[4], int lane) {
    const int N = R * 32;
#pragma unroll
    for (int k = 2; k <= N; k <<= 1) {
#pragma unroll
        for (int j = k >> 1; j > 0; j >>= 1) {
            if (j >= 32) {
                int rj = j >> 5;
#pragma unroll
                for (int r = 0; r < R; r++) {
                    if ((r & rj) == 0) {
                        int rp = r | rj;
                        int e = r * 32 + lane;
                        bool desc = ((e & k) == 0);
                        u64 A = key[r], Bv = key[rp];
                        if (desc ? (A < Bv) : (A > Bv)) { key[r] = Bv; key[rp] = A; }
                    }
                }
            } else {
#pragma unroll
                for (int r = 0; r < R; r++) {
                    u64 other = __shfl_xor_sync(FULL, key[r], j);
                    int e = r * 32 + lane;
                    bool desc = ((e & k) == 0);
                    bool lower = ((lane & j) == 0);
                    if (desc == lower) key[r] = (key[r] > other) ? key[r] : other;
                    else               key[r] = (key[r] < other) ? key[r] : other;
                }
            }
        }
    }
}

// -------- kernel 1: fused decode + dual-anchor softmax + threshold filter ------
__device__ __forceinline__ void push_cand2(float e, int cm1, bool cvalid,
                                           int b, int a, float s, float pre) {
    if (cvalid && e > pre) {
        float p = __fdiv_rn(e, s);
        if (p > 0.05f) {
            int li = b * CM1 + cm1;
            int pos = atomicAdd(&g_candCnt[li], 1);
            if (pos < CAP)
                g_cand[(size_t)li * CAP + pos] =
                    ((u64)__float_as_uint(p) << 32) | (u32)(~(u32)a);
        }
    }
}

__global__ void __launch_bounds__(256) k_cand(const float* __restrict__ logits,
                                              const float* __restrict__ box_reg,
                                              const float* __restrict__ priors) {
    // decode prologue: one thread per (b,a), first 809 blocks only
    int di = blockIdx.x * 256 + threadIdx.x;
    if (di < BATCH * NA) {
        int da = di % NA;
        float4 loc = ((const float4*)box_reg)[di];
        float4 pr  = ((const float4*)priors)[da];
        float pw = pr.z - pr.x, ph = pr.w - pr.y;
        float cx = pr.x + 0.5f * pw, cy = pr.y + 0.5f * ph;
        float x = loc.x * 0.1f * pw + cx;
        float y = loc.y * 0.1f * ph + cy;
        float w = exp_acc(loc.z * 0.2f) * pw;
        float h = exp_acc(loc.w * 0.2f) * ph;
        g_boxes[di] = make_float4(x - w * 0.5f, y - h * 0.5f, x + w * 0.5f, y + h * 0.5f);
    }

    // two anchors per warp, fully interleaved
    int gw = di >> 5;
    int lane = threadIdx.x & 31;
    int idx0 = gw * 2;
    int idx1 = idx0 + 1;
    if (idx0 >= BATCH * NA) return;
    int b0 = idx0 / NA, a0 = idx0 - b0 * NA;
    int b1 = b0, a1 = a0 + 1;
    if (a1 == NA) { b1 = b0 + 1; a1 = 0; }
    const float* LA = logits + (size_t)idx0 * NC;
    const float* LB = logits + (size_t)idx1 * NC;
    bool t2 = lane < NC - 64;

    float al0 = LA[lane];
    float al1 = LA[lane + 32];
    float al2 = t2 ? LA[lane + 64] : -1e30f;
    float bl0 = LB[lane];
    float bl1 = LB[lane + 32];
    float bl2 = t2 ? LB[lane + 64] : -1e30f;

    u32 oma = max(f2ord(al0), max(f2ord(al1), f2ord(al2)));
    u32 omb = max(f2ord(bl0), max(f2ord(bl1), f2ord(bl2)));
    float mxa = ord2f(__reduce_max_sync(FULL, oma));
    float mxb = ord2f(__reduce_max_sync(FULL, omb));

    // packed exps: lo half = anchor0, hi half = anchor1 (bit-identical per half)
    u64 x0 = pk2(al0 - mxa, bl0 - mxb);
    u64 x1 = pk2(al1 - mxa, bl1 - mxb);
    u64 xv2 = pk2(al2 - mxa, bl2 - mxb);
    u64 e0p = exp_acc2(x0);
    u64 e1p = exp_acc2(x1);
    u64 e2p = t2 ? exp_acc2(xv2) : 0ULL;

    // packed sum (same left association per half as scalar)
    u64 pk;
    ADD2(pk, e0p, e1p);
    ADD2(pk, pk, e2p);
#pragma unroll
    for (int o = 16; o; o >>= 1) {
        u64 other = __shfl_xor_sync(FULL, pk, o);
        ADD2(pk, pk, other);
    }
    float sa, sb;
    upk2(pk, sa, sb);

    float ea0, eb0, ea1, eb1, ea2, eb2;
    upk2(e0p, ea0, eb0);
    upk2(e1p, ea1, eb1);
    upk2(e2p, ea2, eb2);

    float prea = 0.0495f * sa;
    float preb = 0.0495f * sb;
    bool l0v = lane > 0;
    push_cand2(ea0, lane - 1,  l0v,  b0, a0, sa, prea);
    push_cand2(eb0, lane - 1,  l0v,  b1, a1, sb, preb);
    push_cand2(ea1, lane + 31, true, b0, a0, sa, prea);
    push_cand2(eb1, lane + 31, true, b1, a1, sb, preb);
    push_cand2(ea2, lane + 63, true, b0, a0, sa, prea);
    push_cand2(eb2, lane + 63, true, b1, a1, sb, preb);
}

// -------- kernel 2: warp-per-class NMS (shared masks, lane-0 scan) --------
__global__ void __launch_bounds__(128) k_nms_warp() {
    __shared__ float4 sbox[4][128];
    __shared__ float  sarea[4][128];
    __shared__ u32    smask[4][128 * 4];

    int wid = threadIdx.x >> 5;
    int lane = threadIdx.x & 31;
    int li = blockIdx.x * 4 + wid;
    if (li >= BATCH * CM1) return;
    int b = li / CM1;
    int c = li - b * CM1;

    int m = g_candCnt[li];
    if (m == 0) return;
    if (m > 128) {                         // rare fallback, handled in k_top
        if (lane == 0) {
            int p = atomicAdd(&g_bigCnt, 1);
            g_bigList[p] = li;
        }
        return;
    }

    u64 key[4];
#pragma unroll
    for (int r = 0; r < 4; r++) {
        int e = r * 32 + lane;
        key[r] = (e < m) ? g_cand[(size_t)li * CAP + e] : 0ULL;
    }

    if (m <= 64) warp_bitonic_desc<2>(key, lane);   // 21 stages, 2 keys/lane
    else         warp_bitonic_desc<4>(key, lane);   // 28 stages, 4 keys/lane

    int K = m;   // <= 128 <= KMAX

#pragma unroll
    for (int r = 0; r < 4; r++) {
        int e = r * 32 + lane;
        if (e < K) {
            int a = (int)(~(u32)key[r]);
            float4 bb = g_boxes[b * NA + a];
            sbox[wid][e] = bb;
            sarea[wid][e] = fmaxf(bb.z - bb.x, 0.f) * fmaxf(bb.w - bb.y, 0.f);
        }
    }
    __syncwarp();

    // suppression rows: load-balanced row map {lane, 63-lane, 64+lane, 127-lane}
    int lastseg = (K - 1) >> 5;
#pragma unroll
    for (int rr = 0; rr < 4; rr++) {
        int i;
        if (rr == 0)      i = lane;
        else if (rr == 1) i = 63 - lane;
        else if (rr == 2) i = 64 + lane;
        else              i = 127 - lane;
        if (i < K) {
            float4 bi = sbox[wid][i];
            float ai = sarea[wid][i];
#pragma unroll
            for (int seg = 0; seg < 4; seg++) {
                u32 bits = 0;
                if (seg <= lastseg) {
                    int j0 = seg << 5; if (j0 < i + 1) j0 = i + 1;
                    int je = (seg << 5) + 32; if (je > K) je = K;
                    for (int j = j0; j < je; j++) {
                        float4 bj = sbox[wid][j];
                        float iw = fminf(bi.z, bj.z) - fmaxf(bi.x, bj.x);
                        float ih = fminf(bi.w, bj.w) - fmaxf(bi.y, bj.y);
                        iw = fmaxf(iw, 0.f); ih = fmaxf(ih, 0.f);
                        float inter = iw * ih;
                        float sum = ai + sarea[wid][j];
                        if (inter > 0.332f * sum) {      // superset prefilter
                            float uni = sum - inter;
                            if (__fdiv_rn(inter, fmaxf(uni, 1e-9f)) > 0.5f)
                                bits |= 1u << (j & 31);
                        }
                    }
                }
                smask[wid][i * 4 + seg] = bits;
            }
        }
    }
    __syncwarp();

    u32 kw0 = 0, kw1 = 0, kw2 = 0, kw3 = 0;
    int base = 0;
    if (lane == 0) {
        u32 rem[4];
#pragma unroll
        for (int w = 0; w < 4; w++) {
            int lo = w * 32;
            rem[w] = (K >= lo + 32) ? 0xffffffffu : (K > lo ? ((1u << (K - lo)) - 1u) : 0u);
        }
        u32 kw[4] = {0, 0, 0, 0};
#pragma unroll
        for (int w = 0; w < 4; w++) {
            while (rem[w]) {
                int bit = __ffs(rem[w]) - 1;
                int i = w * 32 + bit;
                kw[w] |= 1u << bit;
                rem[w] &= ~(1u << bit);
                uint4 row = *(const uint4*)&smask[wid][i * 4];
                rem[0] &= ~row.x; rem[1] &= ~row.y;
                rem[2] &= ~row.z; rem[3] &= ~row.w;
            }
        }
        int nkeep = __popc(kw[0]) + __popc(kw[1]) + __popc(kw[2]) + __popc(kw[3]);
        base = atomicAdd(&g_poolCnt[b], nkeep);
        kw0 = kw[0]; kw1 = kw[1]; kw2 = kw[2]; kw3 = kw[3];
    }
    kw0 = __shfl_sync(FULL, kw0, 0);
    kw1 = __shfl_sync(FULL, kw1, 0);
    kw2 = __shfl_sync(FULL, kw2, 0);
    kw3 = __shfl_sync(FULL, kw3, 0);
    base = __shfl_sync(FULL, base, 0);

    int pre1 = __popc(kw0);
    int pre2 = pre1 + __popc(kw1);
    int pre3 = pre2 + __popc(kw2);
#pragma unroll
    for (int r = 0; r < 4; r++) {
        int e = r * 32 + lane;
        u32 kwr = (r == 0) ? kw0 : (r == 1) ? kw1 : (r == 2) ? kw2 : kw3;
        int prer = (r == 0) ? 0 : (r == 1) ? pre1 : (r == 2) ? pre2 : pre3;
        if (e < K && ((kwr >> lane) & 1u)) {
            int rank = prer + __popc(kwr & ((1u << lane) - 1u));
            u64 kk = key[r];
            int a = (int)(~(u32)kk) & 0xFFF;
            int flat = c * KMAX + e;
            u64 det = (kk & 0xFFFFFFFF00000000ULL)
                    | ((u64)(u32)(32767 - flat) << 17)
                    | ((u64)(u32)a << 5);
            int pos = base + rank;
            if (pos < POOLCAP) g_pool[(size_t)b * POOLCAP + pos] = det;
        }
    }
}

// score bucket: monotonic linear map of score (0,1] -> 0..4095
__device__ __forceinline__ int score_bucket(u64 kk) {
    float sc = __uint_as_float((u32)(kk >> 32));
    int d = (int)(sc * 4096.0f);
    return d > 4095 ? 4095 : d;
}

// -------- kernel 3: big-class fallback + 1-pass score-hist top-100 + re-zero ----
__global__ void __launch_bounds__(1024) k_top(float* __restrict__ out) {
    __shared__ int hist[4096];
    __shared__ int segs[256];
    __shared__ u64 sel[128];
    __shared__ int sh_cnt;
    __shared__ u64 sh_prefix;
    __shared__ int sh_rem, sh_total, sh_d;
    __shared__ u64 fkeys[CAP];
    __shared__ float4 fbox[KMAX];
    __shared__ float farea[KMAX];
    __shared__ u32 fmask[KMAX * WMAX];
    __shared__ int fkl[KMAX];
    __shared__ int f_nk, f_base;

    int b = blockIdx.x, tid = threadIdx.x;

    // ---- rare fallback: block-level NMS for this image's m>128 classes ----
    int nbig = g_bigCnt;
    for (int idx = 0; idx < nbig; idx++) {
        int li = g_bigList[idx];
        if (li / CM1 != b) continue;
        int c = li - b * CM1;
        int mm = g_candCnt[li];
        if (mm > CAP) mm = CAP;

        int n = 1; while (n < mm) n <<= 1;
        for (int i = tid; i < n; i += 1024)
            fkeys[i] = (i < mm) ? g_cand[(size_t)li * CAP + i] : 0ULL;
        __syncthreads();
        for (int k = 2; k <= n; k <<= 1)
            for (int j = k >> 1; j > 0; j >>= 1) {
                for (int i = tid; i < n; i += 1024) {
                    int x = i ^ j;
                    if (x > i) {
                        u64 A = fkeys[i], Bv = fkeys[x];
                        bool up = (i & k) == 0;
                        if (up ? (A < Bv) : (A > Bv)) { fkeys[i] = Bv; fkeys[x] = A; }
                    }
                }
                __syncthreads();
            }

        int K = mm < KMAX ? mm : KMAX;
        for (int r = tid; r < K; r += 1024) {
            int a = (int)(~(u32)fkeys[r]);
            float4 bb = g_boxes[b * NA + a];
            fbox[r] = bb;
            farea[r] = fmaxf(bb.z - bb.x, 0.f) * fmaxf(bb.w - bb.y, 0.f);
        }
        __syncthreads();

        int W = (K + 31) >> 5;
        for (int w = tid; w < K * W; w += 1024) {
            int i = w / W, seg = w - i * W;
            u32 bits = 0;
            float4 bi = fbox[i];
            float ai = farea[i];
            int j0 = seg << 5;
            int je = min(j0 + 32, K);
            for (int j = max(j0, i + 1); j < je; j++) {
                float4 bj = fbox[j];
                float iw = fminf(bi.z, bj.z) - fmaxf(bi.x, bj.x);
                float ih = fminf(bi.w, bj.w) - fmaxf(bi.y, bj.y);
                iw = fmaxf(iw, 0.f); ih = fmaxf(ih, 0.f);
                float inter = iw * ih;
                float uni = ai + farea[j] - inter;
                if (inter > 0.4985f * uni)
                    if (__fdiv_rn(inter, fmaxf(uni, 1e-9f)) > 0.5f)
                        bits |= 1u << (j - j0);
            }
            fmask[i * W + seg] = bits;
        }
        __syncthreads();

        if (tid == 0) {
            u32 remv[WMAX] = {0, 0, 0, 0, 0, 0, 0};
            int nkeep = 0;
            for (int i = 0; i < K; i++) {
                if (!((remv[i >> 5] >> (i & 31)) & 1u)) {
                    fkl[nkeep++] = i;
                    for (int w = 0; w < W; w++) remv[w] |= fmask[i * W + w];
                }
            }
            f_nk = nkeep;
            f_base = atomicAdd(&g_poolCnt[b], nkeep);
        }
        __syncthreads();

        int nk = f_nk, bse = f_base;
        for (int sidx = tid; sidx < nk; sidx += 1024) {
            int i = fkl[sidx];
            u64 kk = fkeys[i];
            int a = (int)(~(u32)kk) & 0xFFF;
            int flat = c * KMAX + i;
            u64 det = (kk & 0xFFFFFFFF00000000ULL)
                    | ((u64)(u32)(32767 - flat) << 17)
                    | ((u64)(u32)a << 5);
            int pos = bse + sidx;
            if (pos < POOLCAP) g_pool[(size_t)b * POOLCAP + pos] = det;
        }
        __syncthreads();
    }

    // ---- selection: 1-pass linear-score histogram (fallback: exact u64 radix) ----
    int m = g_poolCnt[b]; if (m > POOLCAP) m = POOLCAP;
    const u64* pool = g_pool + (size_t)b * POOLCAP;

    u64 kth = 0;        // used by fallback path
    int dstar = -1;     // used by fast path (bucket threshold)
    if (m > 100) {
        // fast path: histogram over score buckets
        for (int d = tid; d < 4096; d += 1024) hist[d] = 0;
        __syncthreads();
        for (int i = tid; i < m; i += 1024)
            atomicAdd(&hist[score_bucket(pool[i])], 1);
        __syncthreads();
        if (tid < 256) {
            int s = 0;
#pragma unroll
            for (int q = 0; q < 16; q++) s += hist[tid * 16 + q];
            segs[tid] = s;
        }
        __syncthreads();
        if (tid < 32) {
            int sv[8]; int lsum = 0;
#pragma unroll
            for (int q = 0; q < 8; q++) { sv[q] = segs[tid * 8 + q]; lsum += sv[q]; }
            int acc = lsum;
#pragma unroll
            for (int off = 1; off < 32; off <<= 1) {
                int v = __shfl_down_sync(FULL, acc, off);
                if (tid + off < 32) acc += v;
            }
            int run = acc - lsum;
#pragma unroll
            for (int q = 7; q >= 0; q--) { run += sv[q]; segs[tid * 8 + q] = run; }
        }
        __syncthreads();
        if (tid < 256) {
            int run = (tid < 255) ? segs[tid + 1] : 0;
#pragma unroll
            for (int q = 15; q >= 0; q--) {
                int d = tid * 16 + q;
                int ge = run + hist[d];
                if (ge >= 100 && run < 100) {
                    sh_d = d;
                    sh_total = ge;
                }
                run = ge;
            }
        }
        __syncthreads();
        if (sh_total <= 128) {
            dstar = sh_d;                       // 1-pass success (typical)
        } else {
            // exact 4-pass u64 radix fallback (rare: >28 keys in one bucket at rank 100)
            u64 prefix = 0; int rem = 100;
            for (int pass = 0; pass < 4; pass++) {
                int shift = 52 - 12 * pass;
                for (int d = tid; d < 4096; d += 1024) hist[d] = 0;
                __syncthreads();
                for (int i = tid; i < m; i += 1024) {
                    u64 kk = pool[i];
                    if (pass == 0 || (kk >> (shift + 12)) == prefix)
                        atomicAdd(&hist[(int)((kk >> shift) & 0xFFF)], 1);
                }
                __syncthreads();
                if (tid < 256) {
                    int s = 0;
#pragma unroll
                    for (int q = 0; q < 16; q++) s += hist[tid * 16 + q];
                    segs[tid] = s;
                }
                __syncthreads();
                if (tid < 32) {
                    int sv[8]; int lsum = 0;
#pragma unroll
                    for (int q = 0; q < 8; q++) { sv[q] = segs[tid * 8 + q]; lsum += sv[q]; }
                    int acc = lsum;
#pragma unroll
                    for (int off = 1; off < 32; off <<= 1) {
                        int v = __shfl_down_sync(FULL, acc, off);
                        if (tid + off < 32) acc += v;
                    }
                    int run = acc - lsum;
#pragma unroll
                    for (int q = 7; q >= 0; q--) { run += sv[q]; segs[tid * 8 + q] = run; }
                }
                __syncthreads();
                if (tid < 256) {
                    int run = (tid < 255) ? segs[tid + 1] : 0;
#pragma unroll
                    for (int q = 15; q >= 0; q--) {
                        int d = tid * 16 + q;
                        int ge = run + hist[d];
                        if (ge >= rem && run < rem) {
                            sh_prefix = (prefix << 12) | (u64)d;
                            sh_rem = rem - run;
                            sh_total = (100 - rem) + ge;
                        }
                        run = ge;
                    }
                }
                __syncthreads();
                prefix = sh_prefix; rem = sh_rem;
                int total = sh_total;
                __syncthreads();
                kth = prefix << shift;
                if (total <= 128) break;
            }
        }
    }

    if (tid == 0) sh_cnt = 0;
    __syncthreads();
    for (int i = tid; i < m; i += 1024) {
        u64 kk = pool[i];
        bool take = (dstar >= 0) ? (score_bucket(kk) >= dstar) : (kk >= kth);
        if (take) {
            int p = atomicAdd(&sh_cnt, 1);
            if (p < 128) sel[p] = kk;
        }
    }
    __syncthreads();
    int cnt = sh_cnt; if (cnt > 128) cnt = 128;
    int nsel = cnt < 100 ? cnt : 100;
    if (tid < 128 && tid >= cnt) sel[tid] = 0;
    __syncthreads();

    if (tid < 32) {
        u64 kk[4];
#pragma unroll
        for (int r = 0; r < 4; r++) kk[r] = sel[r * 32 + tid];
        warp_bitonic_desc<4>(kk, tid);
#pragma unroll
        for (int r = 0; r < 4; r++) sel[r * 32 + tid] = kk[r];
    }
    __syncthreads();

    for (int r = tid; r < 100; r += 1024) {
        float o0 = 0, o1 = 0, o2 = 0, o3 = 0, o4 = 0, o5 = 0;
        if (r < nsel) {
            u64 kk = sel[r];
            float sc = __uint_as_float((u32)(kk >> 32));
            int flat = 32767 - (int)((kk >> 17) & 0x7FFF);
            int cls = flat / 200 + 1;
            int a = (int)((kk >> 5) & 0xFFF);
            float4 bb = g_boxes[b * NA + a];
            o0 = bb.x; o1 = bb.y; o2 = bb.z; o3 = bb.w; o4 = sc; o5 = (float)cls;
        }
        float* op = out + ((size_t)b * 100 + r) * 6;
        op[0] = o0; op[1] = o1; op[2] = o2; op[3] = o3; op[4] = o4; op[5] = o5;
    }

    // ---- re-zero this image's counters for the next replay (after all use) ----
    for (int i = tid; i < CM1; i += 1024) g_candCnt[b * CM1 + i] = 0;
    __syncthreads();
    if (tid == 0) {
        g_poolCnt[b] = 0;
        __threadfence();
        int t = atomicAdd(&g_doneCnt, 1);
        if (t == BATCH - 1) { g_bigCnt = 0; g_doneCnt = 0; }
    }
}

// -------- launch --------
extern "C" void kernel_launch(void* const* d_in, const int* in_sizes, int n_in,
                              void* d_out, int out_size) {
    const float* logits = nullptr;
    const float* boxreg = nullptr;
    const float* priors = nullptr;
    for (int i = 0; i < n_in; i++) {
        if (in_sizes[i] == BATCH * NA * NC) logits = (const float*)d_in[i];
        else if (in_sizes[i] == BATCH * NA * 4) boxreg = (const float*)d_in[i];
        else if (in_sizes[i] == NA * 4) priors = (const float*)d_in[i];
    }
    float* out = (float*)d_out;

    k_cand<<<(BATCH * NA / 2 + 7) / 8, 256>>>(logits, boxreg, priors);
    k_nms_warp<<<(BATCH * CM1 + 3) / 4, 128>>>();
    k_top<<<BATCH, 1024>>>(out);
}

// round 14
// speedup vs baseline: 1.2069x; 1.1655x over previous
#include <cuda_runtime.h>
#include <stdint.h>

#define BATCH   64
#define NA      3234
#define NC      91
#define CM1     90
#define CAP     512
#define KMAX    200
#define WMAX    7
#define POOLCAP 16384
#define NWORK   (BATCH * NA / 2)      // dual-anchor work items
#define CGRID   1184                  // 148 SMs x 8 resident blocks

typedef unsigned long long u64;
typedef unsigned int u32;
#define FULL 0xffffffffu

// -------- scratch (static __device__ — zero-init at load; re-zeroed by k_top) ----
__device__ float4 g_boxes[BATCH * NA];
__device__ u64    g_cand[(size_t)BATCH * CM1 * CAP];
__device__ int    g_candCnt[BATCH * CM1];
__device__ u64    g_pool[(size_t)BATCH * POOLCAP];
__device__ int    g_poolCnt[BATCH];
__device__ int    g_bigCnt;
__device__ int    g_bigList[BATCH * CM1];
__device__ int    g_doneCnt;

// ~1-ulp exp, FMA-only (immune to fast-math substitution).
__device__ __forceinline__ float exp_acc(float x) {
    float k = rintf(x * 1.44269504088896340736f);
    float r = fmaf(k, -0.693359375f, x);
    r = fmaf(k, 2.12194440054690582762e-4f, r);
    float p = 1.98412698412698413e-4f;
    p = fmaf(p, r, 1.38888888888888889e-3f);
    p = fmaf(p, r, 8.33333333333333333e-3f);
    p = fmaf(p, r, 4.16666666666666667e-2f);
    p = fmaf(p, r, 1.66666666666666667e-1f);
    p = fmaf(p, r, 0.5f);
    p = fmaf(p, r, 1.0f);
    p = fmaf(p, r, 1.0f);
    int ki = (int)k;
    ki = max(-126, min(126, ki));
    return p * __int_as_float((ki + 127) << 23);
}

__device__ __forceinline__ u32 f2ord(float x) {
    u32 u = __float_as_uint(x);
    return (u & 0x80000000u) ? ~u : (u | 0x80000000u);
}
__device__ __forceinline__ float ord2f(u32 k) {
    u32 u = (k & 0x80000000u) ? (k ^ 0x80000000u) : ~k;
    return __uint_as_float(u);
}

// ---- packed f32x2 helpers (sm_103a) ----
#define MUL2(d, a, b)    asm("mul.rn.f32x2 %0, %1, %2;" : "=l"(d) : "l"(a), "l"(b))
#define ADD2(d, a, b)    asm("add.rn.f32x2 %0, %1, %2;" : "=l"(d) : "l"(a), "l"(b))
#define FMA2(d, a, b, c) asm("fma.rn.f32x2 %0, %1, %2, %3;" : "=l"(d) : "l"(a), "l"(b), "l"(c))

__device__ __forceinline__ u64 pk2(float lo, float hi) {
    u64 r; asm("mov.b64 %0, {%1, %2};" : "=l"(r) : "f"(lo), "f"(hi)); return r;
}
__device__ __forceinline__ void upk2(u64 v, float& lo, float& hi) {
    asm("mov.b64 {%0, %1}, %2;" : "=f"(lo), "=f"(hi) : "l"(v));
}
__device__ __forceinline__ u64 dupc(float f) {
    u32 u = __float_as_uint(f);
    return ((u64)u << 32) | (u64)u;
}

// packed dual exp — per-half bit-identical to exp_acc:
// rint via magic add (RN ties-even == rintf); integer k read from float bits.
__device__ __forceinline__ u64 exp_acc2(u64 x2) {
    u64 t, km, k2, r, p;
    MUL2(t, x2, dupc(1.44269504088896340736f));
    ADD2(km, t, dupc(12582912.0f));            // 1.5*2^23: km = magic + rint(t)
    ADD2(k2, km, dupc(-12582912.0f));          // k = rint(t), exact
    FMA2(r, k2, dupc(-0.693359375f), x2);
    FMA2(r, k2, dupc(2.12194440054690582762e-4f), r);
    p = dupc(1.98412698412698413e-4f);
    FMA2(p, p, r, dupc(1.38888888888888889e-3f));
    FMA2(p, p, r, dupc(8.33333333333333333e-3f));
    FMA2(p, p, r, dupc(4.16666666666666667e-2f));
    FMA2(p, p, r, dupc(1.66666666666666667e-1f));
    FMA2(p, p, r, dupc(0.5f));
    FMA2(p, p, r, dupc(1.0f));
    FMA2(p, p, r, dupc(1.0f));
    int kia = (int)((u32)km - 0x4B400000u);    // integer k, low half
    int kib = (int)((u32)(km >> 32) - 0x4B400000u);
    kia = max(-126, min(126, kia));
    kib = max(-126, min(126, kib));
    u64 sc = ((u64)((u32)(kib + 127) << 23) << 32) | (u32)((kia + 127) << 23);
    u64 out;
    MUL2(out, p, sc);
    return out;
}

// warp-collective descending bitonic sort, R u64 keys per lane (N = 32*R).
template <int R>
__device__ __forceinline__ void warp_bitonic_desc(u64 key[4], int lane) {
    const int N = R * 32;
#pragma unroll
    for (int k = 2; k <= N; k <<= 1) {
#pragma unroll
        for (int j = k >> 1; j > 0; j >>= 1) {
            if (j >= 32) {
                int rj = j >> 5;
#pragma unroll
                for (int r = 0; r < R; r++) {
                    if ((r & rj) == 0) {
                        int rp = r | rj;
                        int e = r * 32 + lane;
                        bool desc = ((e & k) == 0);
                        u64 A = key[r], Bv = key[rp];
                        if (desc ? (A < Bv) : (A > Bv)) { key[r] = Bv; key[rp] = A; }
                    }
                }
            } else {
#pragma unroll
                for (int r = 0; r < R; r++) {
                    u64 other = __shfl_xor_sync(FULL, key[r], j);
                    int e = r * 32 + lane;
                    bool desc = ((e & k) == 0);
                    bool lower = ((lane & j) == 0);
                    if (desc == lower) key[r] = (key[r] > other) ? key[r] : other;
                    else               key[r] = (key[r] < other) ? key[r] : other;
                }
            }
        }
    }
}

// -------- kernel 1: persistent fused decode + dual-anchor softmax + filter ------
__device__ __forceinline__ void push_cand2(float e, int cm1, bool cvalid,
                                           int b, int a, float s, float pre) {
    if (cvalid && e > pre) {
        float p = __fdiv_rn(e, s);
        if (p > 0.05f) {
            int li = b * CM1 + cm1;
            int pos = atomicAdd(&g_candCnt[li], 1);
            if (pos < CAP)
                g_cand[(size_t)li * CAP + pos] =
                    ((u64)__float_as_uint(p) << 32) | (u32)(~(u32)a);
        }
    }
}

__global__ void __launch_bounds__(256) k_cand(const float* __restrict__ logits,
                                              const float* __restrict__ box_reg,
                                              const float* __restrict__ priors) {
    // decode: grid-stride, one thread per (b,a)
    for (int di = blockIdx.x * 256 + threadIdx.x; di < BATCH * NA;
         di += gridDim.x * 256) {
        int da = di % NA;
        float4 loc = ((const float4*)box_reg)[di];
        float4 pr  = ((const float4*)priors)[da];
        float pw = pr.z - pr.x, ph = pr.w - pr.y;
        float cx = pr.x + 0.5f * pw, cy = pr.y + 0.5f * ph;
        float x = loc.x * 0.1f * pw + cx;
        float y = loc.y * 0.1f * ph + cy;
        float w = exp_acc(loc.z * 0.2f) * pw;
        float h = exp_acc(loc.w * 0.2f) * ph;
        g_boxes[di] = make_float4(x - w * 0.5f, y - h * 0.5f, x + w * 0.5f, y + h * 0.5f);
    }

    // softmax+filter: grid-stride over dual-anchor work items, one per warp
    int lane = threadIdx.x & 31;
    int wid = threadIdx.x >> 5;
    for (int gw = blockIdx.x * 8 + wid; gw < NWORK; gw += gridDim.x * 8) {
        int idx0 = gw * 2;
        int idx1 = idx0 + 1;
        int b0 = idx0 / NA, a0 = idx0 - b0 * NA;
        int b1 = b0, a1 = a0 + 1;
        if (a1 == NA) { b1 = b0 + 1; a1 = 0; }
        const float* LA = logits + (size_t)idx0 * NC;
        const float* LB = logits + (size_t)idx1 * NC;
        bool t2 = lane < NC - 64;

        float al0 = LA[lane];
        float al1 = LA[lane + 32];
        float al2 = t2 ? LA[lane + 64] : -1e30f;
        float bl0 = LB[lane];
        float bl1 = LB[lane + 32];
        float bl2 = t2 ? LB[lane + 64] : -1e30f;

        u32 oma = max(f2ord(al0), max(f2ord(al1), f2ord(al2)));
        u32 omb = max(f2ord(bl0), max(f2ord(bl1), f2ord(bl2)));
        float mxa = ord2f(__reduce_max_sync(FULL, oma));
        float mxb = ord2f(__reduce_max_sync(FULL, omb));

        // packed exps: lo half = anchor0, hi half = anchor1 (bit-identical per half)
        u64 x0 = pk2(al0 - mxa, bl0 - mxb);
        u64 x1 = pk2(al1 - mxa, bl1 - mxb);
        u64 xv2 = pk2(al2 - mxa, bl2 - mxb);
        u64 e0p = exp_acc2(x0);
        u64 e1p = exp_acc2(x1);
        u64 e2p = t2 ? exp_acc2(xv2) : 0ULL;

        u64 pk;
        ADD2(pk, e0p, e1p);
        ADD2(pk, pk, e2p);
#pragma unroll
        for (int o = 16; o; o >>= 1) {
            u64 other = __shfl_xor_sync(FULL, pk, o);
            ADD2(pk, pk, other);
        }
        float sa, sb;
        upk2(pk, sa, sb);

        float ea0, eb0, ea1, eb1, ea2, eb2;
        upk2(e0p, ea0, eb0);
        upk2(e1p, ea1, eb1);
        upk2(e2p, ea2, eb2);

        float prea = 0.0495f * sa;
        float preb = 0.0495f * sb;
        bool l0v = lane > 0;
        push_cand2(ea0, lane - 1,  l0v,  b0, a0, sa, prea);
        push_cand2(eb0, lane - 1,  l0v,  b1, a1, sb, preb);
        push_cand2(ea1, lane + 31, true, b0, a0, sa, prea);
        push_cand2(eb1, lane + 31, true, b1, a1, sb, preb);
        push_cand2(ea2, lane + 63, true, b0, a0, sa, prea);
        push_cand2(eb2, lane + 63, true, b1, a1, sb, preb);
    }
}

// -------- kernel 2: warp-per-class NMS (shared masks, lane-0 scan) --------
__global__ void __launch_bounds__(128) k_nms_warp() {
    __shared__ float4 sbox[4][128];
    __shared__ float  sarea[4][128];
    __shared__ u32    smask[4][128 * 4];

    int wid = threadIdx.x >> 5;
    int lane = threadIdx.x & 31;
    int li = blockIdx.x * 4 + wid;
    if (li >= BATCH * CM1) return;
    int b = li / CM1;
    int c = li - b * CM1;

    int m = g_candCnt[li];
    if (m == 0) return;
    if (m > 128) {                         // rare fallback, handled in k_top
        if (lane == 0) {
            int p = atomicAdd(&g_bigCnt, 1);
            g_bigList[p] = li;
        }
        return;
    }

    u64 key[4];
#pragma unroll
    for (int r = 0; r < 4; r++) {
        int e = r * 32 + lane;
        key[r] = (e < m) ? g_cand[(size_t)li * CAP + e] : 0ULL;
    }

    if (m <= 64) warp_bitonic_desc<2>(key, lane);   // 21 stages, 2 keys/lane
    else         warp_bitonic_desc<4>(key, lane);   // 28 stages, 4 keys/lane

    int K = m;   // <= 128 <= KMAX

#pragma unroll
    for (int r = 0; r < 4; r++) {
        int e = r * 32 + lane;
        if (e < K) {
            int a = (int)(~(u32)key[r]);
            float4 bb = g_boxes[b * NA + a];
            sbox[wid][e] = bb;
            sarea[wid][e] = fmaxf(bb.z - bb.x, 0.f) * fmaxf(bb.w - bb.y, 0.f);
        }
    }
    __syncwarp();

    // suppression rows: load-balanced row map {lane, 63-lane, 64+lane, 127-lane}
    int lastseg = (K - 1) >> 5;
#pragma unroll
    for (int rr = 0; rr < 4; rr++) {
        int i;
        if (rr == 0)      i = lane;
        else if (rr == 1) i = 63 - lane;
        else if (rr == 2) i = 64 + lane;
        else              i = 127 - lane;
        if (i < K) {
            float4 bi = sbox[wid][i];
            float ai = sarea[wid][i];
#pragma unroll
            for (int seg = 0; seg < 4; seg++) {
                u32 bits = 0;
                if (seg <= lastseg) {
                    int j0 = seg << 5; if (j0 < i + 1) j0 = i + 1;
                    int je = (seg << 5) + 32; if (je > K) je = K;
                    for (int j = j0; j < je; j++) {
                        float4 bj = sbox[wid][j];
                        float iw = fminf(bi.z, bj.z) - fmaxf(bi.x, bj.x);
                        float ih = fminf(bi.w, bj.w) - fmaxf(bi.y, bj.y);
                        iw = fmaxf(iw, 0.f); ih = fmaxf(ih, 0.f);
                        float inter = iw * ih;
                        float sum = ai + sarea[wid][j];
                        if (inter > 0.332f * sum) {      // superset prefilter
                            float uni = sum - inter;
                            if (__fdiv_rn(inter, fmaxf(uni, 1e-9f)) > 0.5f)
                                bits |= 1u << (j & 31);
                        }
                    }
                }
                smask[wid][i * 4 + seg] = bits;
            }
        }
    }
    __syncwarp();

    u32 kw0 = 0, kw1 = 0, kw2 = 0, kw3 = 0;
    int base = 0;
    if (lane == 0) {
        u32 rem[4];
#pragma unroll
        for (int w = 0; w < 4; w++) {
            int lo = w * 32;
            rem[w] = (K >= lo + 32) ? 0xffffffffu : (K > lo ? ((1u << (K - lo)) - 1u) : 0u);
        }
        u32 kw[4] = {0, 0, 0, 0};
#pragma unroll
        for (int w = 0; w < 4; w++) {
            while (rem[w]) {
                int bit = __ffs(rem[w]) - 1;
                int i = w * 32 + bit;
                kw[w] |= 1u << bit;
                rem[w] &= ~(1u << bit);
                uint4 row = *(const uint4*)&smask[wid][i * 4];
                rem[0] &= ~row.x; rem[1] &= ~row.y;
                rem[2] &= ~row.z; rem[3] &= ~row.w;
            }
        }
        int nkeep = __popc(kw[0]) + __popc(kw[1]) + __popc(kw[2]) + __popc(kw[3]);
        base = atomicAdd(&g_poolCnt[b], nkeep);
        kw0 = kw[0]; kw1 = kw[1]; kw2 = kw[2]; kw3 = kw[3];
    }
    kw0 = __shfl_sync(FULL, kw0, 0);
    kw1 = __shfl_sync(FULL, kw1, 0);
    kw2 = __shfl_sync(FULL, kw2, 0);
    kw3 = __shfl_sync(FULL, kw3, 0);
    base = __shfl_sync(FULL, base, 0);

    int pre1 = __popc(kw0);
    int pre2 = pre1 + __popc(kw1);
    int pre3 = pre2 + __popc(kw2);
#pragma unroll
    for (int r = 0; r < 4; r++) {
        int e = r * 32 + lane;
        u32 kwr = (r == 0) ? kw0 : (r == 1) ? kw1 : (r == 2) ? kw2 : kw3;
        int prer = (r == 0) ? 0 : (r == 1) ? pre1 : (r == 2) ? pre2 : pre3;
        if (e < K && ((kwr >> lane) & 1u)) {
            int rank = prer + __popc(kwr & ((1u << lane) - 1u));
            u64 kk = key[r];
            int a = (int)(~(u32)kk) & 0xFFF;
            int flat = c * KMAX + e;
            u64 det = (kk & 0xFFFFFFFF00000000ULL)
                    | ((u64)(u32)(32767 - flat) << 17)
                    | ((u64)(u32)a << 5);
            int pos = base + rank;
            if (pos < POOLCAP) g_pool[(size_t)b * POOLCAP + pos] = det;
        }
    }
}

// score bucket: monotonic linear map of score (0,1] -> 0..4095
__device__ __forceinline__ int score_bucket(u64 kk) {
    float sc = __uint_as_float((u32)(kk >> 32));
    int d = (int)(sc * 4096.0f);
    return d > 4095 ? 4095 : d;
}

// -------- kernel 3: big-class fallback + 1-pass score-hist top-100 + re-zero ----
__global__ void __launch_bounds__(1024) k_top(float* __restrict__ out) {
    __shared__ int hist[4096];
    __shared__ int segs[256];
    __shared__ u64 sel[128];
    __shared__ int sh_cnt;
    __shared__ u64 sh_prefix;
    __shared__ int sh_rem, sh_total, sh_d;
    __shared__ u64 fkeys[CAP];
    __shared__ float4 fbox[KMAX];
    __shared__ float farea[KMAX];
    __shared__ u32 fmask[KMAX * WMAX];
    __shared__ int fkl[KMAX];
    __shared__ int f_nk, f_base;

    int b = blockIdx.x, tid = threadIdx.x;

    // ---- rare fallback: block-level NMS for this image's m>128 classes ----
    int nbig = g_bigCnt;
    for (int idx = 0; idx < nbig; idx++) {
        int li = g_bigList[idx];
        if (li / CM1 != b) continue;
        int c = li - b * CM1;
        int mm = g_candCnt[li];
        if (mm > CAP) mm = CAP;

        int n = 1; while (n < mm) n <<= 1;
        for (int i = tid; i < n; i += 1024)
            fkeys[i] = (i < mm) ? g_cand[(size_t)li * CAP + i] : 0ULL;
        __syncthreads();
        for (int k = 2; k <= n; k <<= 1)
            for (int j = k >> 1; j > 0; j >>= 1) {
                for (int i = tid; i < n; i += 1024) {
                    int x = i ^ j;
                    if (x > i) {
                        u64 A = fkeys[i], Bv = fkeys[x];
                        bool up = (i & k) == 0;
                        if (up ? (A < Bv) : (A > Bv)) { fkeys[i] = Bv; fkeys[x] = A; }
                    }
                }
                __syncthreads();
            }

        int K = mm < KMAX ? mm : KMAX;
        for (int r = tid; r < K; r += 1024) {
            int a = (int)(~(u32)fkeys[r]);
            float4 bb = g_boxes[b * NA + a];
            fbox[r] = bb;
            farea[r] = fmaxf(bb.z - bb.x, 0.f) * fmaxf(bb.w - bb.y, 0.f);
        }
        __syncthreads();

        int W = (K + 31) >> 5;
        for (int w = tid; w < K * W; w += 1024) {
            int i = w / W, seg = w - i * W;
            u32 bits = 0;
            float4 bi = fbox[i];
            float ai = farea[i];
            int j0 = seg << 5;
            int je = min(j0 + 32, K);
            for (int j = max(j0, i + 1); j < je; j++) {
                float4 bj = fbox[j];
                float iw = fminf(bi.z, bj.z) - fmaxf(bi.x, bj.x);
                float ih = fminf(bi.w, bj.w) - fmaxf(bi.y, bj.y);
                iw = fmaxf(iw, 0.f); ih = fmaxf(ih, 0.f);
                float inter = iw * ih;
                float uni = ai + farea[j] - inter;
                if (inter > 0.4985f * uni)
                    if (__fdiv_rn(inter, fmaxf(uni, 1e-9f)) > 0.5f)
                        bits |= 1u << (j - j0);
            }
            fmask[i * W + seg] = bits;
        }
        __syncthreads();

        if (tid == 0) {
            u32 remv[WMAX] = {0, 0, 0, 0, 0, 0, 0};
            int nkeep = 0;
            for (int i = 0; i < K; i++) {
                if (!((remv[i >> 5] >> (i & 31)) & 1u)) {
                    fkl[nkeep++] = i;
                    for (int w = 0; w < W; w++) remv[w] |= fmask[i * W + w];
                }
            }
            f_nk = nkeep;
            f_base = atomicAdd(&g_poolCnt[b], nkeep);
        }
        __syncthreads();

        int nk = f_nk, bse = f_base;
        for (int sidx = tid; sidx < nk; sidx += 1024) {
            int i = fkl[sidx];
            u64 kk = fkeys[i];
            int a = (int)(~(u32)kk) & 0xFFF;
            int flat = c * KMAX + i;
            u64 det = (kk & 0xFFFFFFFF00000000ULL)
                    | ((u64)(u32)(32767 - flat) << 17)
                    | ((u64)(u32)a << 5);
            int pos = bse + sidx;
            if (pos < POOLCAP) g_pool[(size_t)b * POOLCAP + pos] = det;
        }
        __syncthreads();
    }

    // ---- selection: 1-pass linear-score histogram (fallback: exact u64 radix) ----
    int m = g_poolCnt[b]; if (m > POOLCAP) m = POOLCAP;
    const u64* pool = g_pool + (size_t)b * POOLCAP;

    u64 kth = 0;        // used by fallback path
    int dstar = -1;     // used by fast path (bucket threshold)
    if (m > 100) {
        // fast path: histogram over score buckets
        for (int d = tid; d < 4096; d += 1024) hist[d] = 0;
        __syncthreads();
        for (int i = tid; i < m; i += 1024)
            atomicAdd(&hist[score_bucket(pool[i])], 1);
        __syncthreads();
        if (tid < 256) {
            int s = 0;
#pragma unroll
            for (int q = 0; q < 16; q++) s += hist[tid * 16 + q];
            segs[tid] = s;
        }
        __syncthreads();
        if (tid < 32) {
            int sv[8]; int lsum = 0;
#pragma unroll
            for (int q = 0; q < 8; q++) { sv[q] = segs[tid * 8 + q]; lsum += sv[q]; }
            int acc = lsum;
#pragma unroll
            for (int off = 1; off < 32; off <<= 1) {
                int v = __shfl_down_sync(FULL, acc, off);
                if (tid + off < 32) acc += v;
            }
            int run = acc - lsum;
#pragma unroll
            for (int q = 7; q >= 0; q--) { run += sv[q]; segs[tid * 8 + q] = run; }
        }
        __syncthreads();
        if (tid < 256) {
            int run = (tid < 255) ? segs[tid + 1] : 0;
#pragma unroll
            for (int q = 15; q >= 0; q--) {
                int d = tid * 16 + q;
                int ge = run + hist[d];
                if (ge >= 100 && run < 100) {
                    sh_d = d;
                    sh_total = ge;
                }
                run = ge;
            }
        }
        __syncthreads();
        if (sh_total <= 128) {
            dstar = sh_d;                       // 1-pass success (typical)
        } else {
            // exact 4-pass u64 radix fallback (rare: >28 keys in one bucket at rank 100)
            u64 prefix = 0; int rem = 100;
            for (int pass = 0; pass < 4; pass++) {
                int shift = 52 - 12 * pass;
                for (int d = tid; d < 4096; d += 1024) hist[d] = 0;
                __syncthreads();
                for (int i = tid; i < m; i += 1024) {
                    u64 kk = pool[i];
                    if (pass == 0 || (kk >> (shift + 12)) == prefix)
                        atomicAdd(&hist[(int)((kk >> shift) & 0xFFF)], 1);
                }
                __syncthreads();
                if (tid < 256) {
                    int s = 0;
#pragma unroll
                    for (int q = 0; q < 16; q++) s += hist[tid * 16 + q];
                    segs[tid] = s;
                }
                __syncthreads();
                if (tid < 32) {
                    int sv[8]; int lsum = 0;
#pragma unroll
                    for (int q = 0; q < 8; q++) { sv[q] = segs[tid * 8 + q]; lsum += sv[q]; }
                    int acc = lsum;
#pragma unroll
                    for (int off = 1; off < 32; off <<= 1) {
                        int v = __shfl_down_sync(FULL, acc, off);
                        if (tid + off < 32) acc += v;
                    }
                    int run = acc - lsum;
#pragma unroll
                    for (int q = 7; q >= 0; q--) { run += sv[q]; segs[tid * 8 + q] = run; }
                }
                __syncthreads();
                if (tid < 256) {
                    int run = (tid < 255) ? segs[tid + 1] : 0;
#pragma unroll
                    for (int q = 15; q >= 0; q--) {
                        int d = tid * 16 + q;
                        int ge = run + hist[d];
                        if (ge >= rem && run < rem) {
                            sh_prefix = (prefix << 12) | (u64)d;
                            sh_rem = rem - run;
                            sh_total = (100 - rem) + ge;
                        }
                        run = ge;
                    }
                }
                __syncthreads();
                prefix = sh_prefix; rem = sh_rem;
                int total = sh_total;
                __syncthreads();
                kth = prefix << shift;
                if (total <= 128) break;
            }
        }
    }

    if (tid == 0) sh_cnt = 0;
    __syncthreads();
    for (int i = tid; i < m; i += 1024) {
        u64 kk = pool[i];
        bool take = (dstar >= 0) ? (score_bucket(kk) >= dstar) : (kk >= kth);
        if (take) {
            int p = atomicAdd(&sh_cnt, 1);
            if (p < 128) sel[p] = kk;
        }
    }
    __syncthreads();
    int cnt = sh_cnt; if (cnt > 128) cnt = 128;
    int nsel = cnt < 100 ? cnt : 100;
    if (tid < 128 && tid >= cnt) sel[tid] = 0;
    __syncthreads();

    if (tid < 32) {
        u64 kk[4];
#pragma unroll
        for (int r = 0; r < 4; r++) kk[r] = sel[r * 32 + tid];
        warp_bitonic_desc<4>(kk, tid);
#pragma unroll
        for (int r = 0; r < 4; r++) sel[r * 32 + tid] = kk[r];
    }
    __syncthreads();

    for (int r = tid; r < 100; r += 1024) {
        float o0 = 0, o1 = 0, o2 = 0, o3 = 0, o4 = 0, o5 = 0;
        if (r < nsel) {
            u64 kk = sel[r];
            float sc = __uint_as_float((u32)(kk >> 32));
            int flat = 32767 - (int)((kk >> 17) & 0x7FFF);
            int cls = flat / 200 + 1;
            int a = (int)((kk >> 5) & 0xFFF);
            float4 bb = g_boxes[b * NA + a];
            o0 = bb.x; o1 = bb.y; o2 = bb.z; o3 = bb.w; o4 = sc; o5 = (float)cls;
        }
        float* op = out + ((size_t)b * 100 + r) * 6;
        op[0] = o0; op[1] = o1; op[2] = o2; op[3] = o3; op[4] = o4; op[5] = o5;
    }

    // ---- re-zero this image's counters for the next replay (after all use) ----
    for (int i = tid; i < CM1; i += 1024) g_candCnt[b * CM1 + i] = 0;
    __syncthreads();
    if (tid == 0) {
        g_poolCnt[b] = 0;
        __threadfence();
        int t = atomicAdd(&g_doneCnt, 1);
        if (t == BATCH - 1) { g_bigCnt = 0; g_doneCnt = 0; }
    }
}

// -------- launch --------
extern "C" void kernel_launch(void* const* d_in, const int* in_sizes, int n_in,
                              void* d_out, int out_size) {
    const float* logits = nullptr;
    const float* boxreg = nullptr;
    const float* priors = nullptr;
    for (int i = 0; i < n_in; i++) {
        if (in_sizes[i] == BATCH * NA * NC) logits = (const float*)d_in[i];
        else if (in_sizes[i] == BATCH * NA * 4) boxreg = (const float*)d_in[i];
        else if (in_sizes[i] == NA * 4) priors = (const float*)d_in[i];
    }
    float* out = (float*)d_out;

    k_cand<<<CGRID, 256>>>(logits, boxreg, priors);
    k_nms_warp<<<(BATCH * CM1 + 3) / 4, 128>>>();
    k_top<<<BATCH, 1024>>>(out);
}

// round 16
// speedup vs baseline: 1.2073x; 1.0003x over previous
#include <cuda_runtime.h>
#include <stdint.h>

#define BATCH   64
#define NA      3234
#define NC      91
#define CM1     90
#define CAP     512
#define KMAX    200
#define WMAX    7
#define POOLCAP 16384
#define NWORK   (BATCH * NA / 2)      // dual-anchor work items
#define CGRID   1184                  // 148 SMs x 8 resident blocks

typedef unsigned long long u64;
typedef unsigned int u32;
#define FULL 0xffffffffu

// -------- scratch (static __device__ — zero-init at load; re-zeroed by k_top) ----
__device__ float4 g_boxes[BATCH * NA];
__device__ u64    g_cand[(size_t)BATCH * CM1 * CAP];
__device__ int    g_candCnt[BATCH * CM1];
__device__ u64    g_pool[(size_t)BATCH * POOLCAP];
__device__ int    g_poolCnt[BATCH];
__device__ int    g_bigCnt;
__device__ int    g_bigList[BATCH * CM1];
__device__ int    g_doneCnt;

// ~1-ulp exp, FMA-only (immune to fast-math substitution).
__device__ __forceinline__ float exp_acc(float x) {
    float k = rintf(x * 1.44269504088896340736f);
    float r = fmaf(k, -0.693359375f, x);
    r = fmaf(k, 2.12194440054690582762e-4f, r);
    float p = 1.98412698412698413e-4f;
    p = fmaf(p, r, 1.38888888888888889e-3f);
    p = fmaf(p, r, 8.33333333333333333e-3f);
    p = fmaf(p, r, 4.16666666666666667e-2f);
    p = fmaf(p, r, 1.66666666666666667e-1f);
    p = fmaf(p, r, 0.5f);
    p = fmaf(p, r, 1.0f);
    p = fmaf(p, r, 1.0f);
    int ki = (int)k;
    ki = max(-126, min(126, ki));
    return p * __int_as_float((ki + 127) << 23);
}

__device__ __forceinline__ u32 f2ord(float x) {
    u32 u = __float_as_uint(x);
    return (u & 0x80000000u) ? ~u : (u | 0x80000000u);
}
__device__ __forceinline__ float ord2f(u32 k) {
    u32 u = (k & 0x80000000u) ? (k ^ 0x80000000u) : ~k;
    return __uint_as_float(u);
}

// ---- packed f32x2 helpers (sm_103a; only add/mul/fma exist in this PTX) ----
#define MUL2(d, a, b)    asm("mul.rn.f32x2 %0, %1, %2;" : "=l"(d) : "l"(a), "l"(b))
#define ADD2(d, a, b)    asm("add.rn.f32x2 %0, %1, %2;" : "=l"(d) : "l"(a), "l"(b))
#define FMA2(d, a, b, c) asm("fma.rn.f32x2 %0, %1, %2, %3;" : "=l"(d) : "l"(a), "l"(b), "l"(c))

__device__ __forceinline__ u64 pk2(float lo, float hi) {
    u64 r; asm("mov.b64 %0, {%1, %2};" : "=l"(r) : "f"(lo), "f"(hi)); return r;
}
__device__ __forceinline__ void upk2(u64 v, float& lo, float& hi) {
    asm("mov.b64 {%0, %1}, %2;" : "=f"(lo), "=f"(hi) : "l"(v));
}
__device__ __forceinline__ u64 dupc(float f) {
    u32 u = __float_as_uint(f);
    return ((u64)u << 32) | (u64)u;
}

// packed dual exp — per-half bit-identical to exp_acc:
// rint via magic add (RN ties-even == rintf); integer k read from float bits.
__device__ __forceinline__ u64 exp_acc2(u64 x2) {
    u64 t, km, k2, r, p;
    MUL2(t, x2, dupc(1.44269504088896340736f));
    ADD2(km, t, dupc(12582912.0f));            // 1.5*2^23: km = magic + rint(t)
    ADD2(k2, km, dupc(-12582912.0f));          // k = rint(t), exact
    FMA2(r, k2, dupc(-0.693359375f), x2);
    FMA2(r, k2, dupc(2.12194440054690582762e-4f), r);
    p = dupc(1.98412698412698413e-4f);
    FMA2(p, p, r, dupc(1.38888888888888889e-3f));
    FMA2(p, p, r, dupc(8.33333333333333333e-3f));
    FMA2(p, p, r, dupc(4.16666666666666667e-2f));
    FMA2(p, p, r, dupc(1.66666666666666667e-1f));
    FMA2(p, p, r, dupc(0.5f));
    FMA2(p, p, r, dupc(1.0f));
    FMA2(p, p, r, dupc(1.0f));
    int kia = (int)((u32)km - 0x4B400000u);    // integer k, low half
    int kib = (int)((u32)(km >> 32) - 0x4B400000u);
    kia = max(-126, min(126, kia));
    kib = max(-126, min(126, kib));
    u64 sc = ((u64)((u32)(kib + 127) << 23) << 32) | (u32)((kia + 127) << 23);
    u64 out;
    MUL2(out, p, sc);
    return out;
}

// warp-collective descending bitonic sort, R u64 keys per lane (N = 32*R).
template <int R>
__device__ __forceinline__ void warp_bitonic_desc(u64 key[4], int lane) {
    const int N = R * 32;
#pragma unroll
    for (int k = 2; k <= N; k <<= 1) {
#pragma unroll
        for (int j = k >> 1; j > 0; j >>= 1) {
            if (j >= 32) {
                int rj = j >> 5;
#pragma unroll
                for (int r = 0; r < R; r++) {
                    if ((r & rj) == 0) {
                        int rp = r | rj;
                        int e = r * 32 + lane;
                        bool desc = ((e & k) == 0);
                        u64 A = key[r], Bv = key[rp];
                        if (desc ? (A < Bv) : (A > Bv)) { key[r] = Bv; key[rp] = A; }
                    }
                }
            } else {
#pragma unroll
                for (int r = 0; r < R; r++) {
                    u64 other = __shfl_xor_sync(FULL, key[r], j);
                    int e = r * 32 + lane;
                    bool desc = ((e & k) == 0);
                    bool lower = ((lane & j) == 0);
                    if (desc == lower) key[r] = (key[r] > other) ? key[r] : other;
                    else               key[r] = (key[r] < other) ? key[r] : other;
                }
            }
        }
    }
}

// -------- kernel 1: persistent fused decode + dual-anchor softmax + filter ------
__device__ __forceinline__ void push_cand2(float e, int cm1, bool cvalid,
                                           int b, int a, float s, float pre) {
    if (cvalid && e > pre) {
        float p = __fdiv_rn(e, s);
        if (p > 0.05f) {
            int li = b * CM1 + cm1;
            int pos = atomicAdd(&g_candCnt[li], 1);
            if (pos < CAP)
                g_cand[(size_t)li * CAP + pos] =
                    ((u64)__float_as_uint(p) << 32) | (u32)(~(u32)a);
        }
    }
}

__global__ void __launch_bounds__(256) k_cand(const float* __restrict__ logits,
                                              const float* __restrict__ box_reg,
                                              const float* __restrict__ priors) {
    // decode: grid-stride, one thread per (b,a)
    for (int di = blockIdx.x * 256 + threadIdx.x; di < BATCH * NA;
         di += gridDim.x * 256) {
        int da = di % NA;
        float4 loc = ((const float4*)box_reg)[di];
        float4 pr  = ((const float4*)priors)[da];
        float pw = pr.z - pr.x, ph = pr.w - pr.y;
        float cx = pr.x + 0.5f * pw, cy = pr.y + 0.5f * ph;
        float x = loc.x * 0.1f * pw + cx;
        float y = loc.y * 0.1f * ph + cy;
        float w = exp_acc(loc.z * 0.2f) * pw;
        float h = exp_acc(loc.w * 0.2f) * ph;
        g_boxes[di] = make_float4(x - w * 0.5f, y - h * 0.5f, x + w * 0.5f, y + h * 0.5f);
    }

    // softmax+filter: grid-stride over dual-anchor work items, one per warp
    int lane = threadIdx.x & 31;
    int wid = threadIdx.x >> 5;
    for (int gw = blockIdx.x * 8 + wid; gw < NWORK; gw += gridDim.x * 8) {
        int idx0 = gw * 2;
        int idx1 = idx0 + 1;
        int b0 = idx0 / NA, a0 = idx0 - b0 * NA;
        int b1 = b0, a1 = a0 + 1;
        if (a1 == NA) { b1 = b0 + 1; a1 = 0; }
        const float* LA = logits + (size_t)idx0 * NC;
        const float* LB = logits + (size_t)idx1 * NC;
        bool t2 = lane < NC - 64;

        float al0 = LA[lane];
        float al1 = LA[lane + 32];
        float al2 = t2 ? LA[lane + 64] : -1e30f;
        float bl0 = LB[lane];
        float bl1 = LB[lane + 32];
        float bl2 = t2 ? LB[lane + 64] : -1e30f;

        u32 oma = max(f2ord(al0), max(f2ord(al1), f2ord(al2)));
        u32 omb = max(f2ord(bl0), max(f2ord(bl1), f2ord(bl2)));
        float mxa = ord2f(__reduce_max_sync(FULL, oma));
        float mxb = ord2f(__reduce_max_sync(FULL, omb));

        // packed exps: lo half = anchor0, hi half = anchor1 (bit-identical per half)
        u64 x0 = pk2(al0 - mxa, bl0 - mxb);
        u64 x1 = pk2(al1 - mxa, bl1 - mxb);
        u64 xv2 = pk2(al2 - mxa, bl2 - mxb);
        u64 e0p = exp_acc2(x0);
        u64 e1p = exp_acc2(x1);
        u64 e2p = t2 ? exp_acc2(xv2) : 0ULL;

        u64 pk;
        ADD2(pk, e0p, e1p);
        ADD2(pk, pk, e2p);
#pragma unroll
        for (int o = 16; o; o >>= 1) {
            u64 other = __shfl_xor_sync(FULL, pk, o);
            ADD2(pk, pk, other);
        }
        float sa, sb;
        upk2(pk, sa, sb);

        float ea0, eb0, ea1, eb1, ea2, eb2;
        upk2(e0p, ea0, eb0);
        upk2(e1p, ea1, eb1);
        upk2(e2p, ea2, eb2);

        float prea = 0.0495f * sa;
        float preb = 0.0495f * sb;
        bool l0v = lane > 0;
        push_cand2(ea0, lane - 1,  l0v,  b0, a0, sa, prea);
        push_cand2(eb0, lane - 1,  l0v,  b1, a1, sb, preb);
        push_cand2(ea1, lane + 31, true, b0, a0, sa, prea);
        push_cand2(eb1, lane + 31, true, b1, a1, sb, preb);
        push_cand2(ea2, lane + 63, true, b0, a0, sa, prea);
        push_cand2(eb2, lane + 63, true, b1, a1, sb, preb);
    }
}

// -------- kernel 2: warp-per-class NMS (shared masks, lane-0 scan) --------
__global__ void __launch_bounds__(128) k_nms_warp() {
    __shared__ float4 sbox[4][128];
    __shared__ float  sarea[4][128];
    __shared__ u32    smask[4][128 * 4];

    int wid = threadIdx.x >> 5;
    int lane = threadIdx.x & 31;
    int li = blockIdx.x * 4 + wid;
    if (li >= BATCH * CM1) return;
    int b = li / CM1;
    int c = li - b * CM1;

    int m = g_candCnt[li];
    if (m == 0) return;
    if (m > 128) {                         // rare fallback, handled in k_top
        if (lane == 0) {
            int p = atomicAdd(&g_bigCnt, 1);
            g_bigList[p] = li;
        }
        return;
    }

    u64 key[4];
#pragma unroll
    for (int r = 0; r < 4; r++) {
        int e = r * 32 + lane;
        key[r] = (e < m) ? g_cand[(size_t)li * CAP + e] : 0ULL;
    }

    if (m <= 64) warp_bitonic_desc<2>(key, lane);   // 21 stages, 2 keys/lane
    else         warp_bitonic_desc<4>(key, lane);   // 28 stages, 4 keys/lane

    int K = m;   // <= 128 <= KMAX

#pragma unroll
    for (int r = 0; r < 4; r++) {
        int e = r * 32 + lane;
        if (e < K) {
            int a = (int)(~(u32)key[r]);
            float4 bb = g_boxes[b * NA + a];
            sbox[wid][e] = bb;
            sarea[wid][e] = fmaxf(bb.z - bb.x, 0.f) * fmaxf(bb.w - bb.y, 0.f);
        }
    }
    __syncwarp();

    // suppression rows: load-balanced row map {lane, 63-lane, 64+lane, 127-lane}
    int lastseg = (K - 1) >> 5;
#pragma unroll
    for (int rr = 0; rr < 4; rr++) {
        int i;
        if (rr == 0)      i = lane;
        else if (rr == 1) i = 63 - lane;
        else if (rr == 2) i = 64 + lane;
        else              i = 127 - lane;
        if (i < K) {
            float4 bi = sbox[wid][i];
            float ai = sarea[wid][i];
#pragma unroll
            for (int seg = 0; seg < 4; seg++) {
                u32 bits = 0;
                if (seg <= lastseg) {
                    int j0 = seg << 5; if (j0 < i + 1) j0 = i + 1;
                    int je = (seg << 5) + 32; if (je > K) je = K;
                    for (int j = j0; j < je; j++) {
                        float4 bj = sbox[wid][j];
                        float iw = fminf(bi.z, bj.z) - fmaxf(bi.x, bj.x);
                        float ih = fminf(bi.w, bj.w) - fmaxf(bi.y, bj.y);
                        iw = fmaxf(iw, 0.f); ih = fmaxf(ih, 0.f);
                        float inter = iw * ih;
                        float sum = ai + sarea[wid][j];
                        if (inter > 0.332f * sum) {      // superset prefilter
                            float uni = sum - inter;
                            if (__fdiv_rn(inter, fmaxf(uni, 1e-9f)) > 0.5f)
                                bits |= 1u << (j & 31);
                        }
                    }
                }
                smask[wid][i * 4 + seg] = bits;
            }
        }
    }
    __syncwarp();

    u32 kw0 = 0, kw1 = 0, kw2 = 0, kw3 = 0;
    int base = 0;
    if (lane == 0) {
        u32 rem[4];
#pragma unroll
        for (int w = 0; w < 4; w++) {
            int lo = w * 32;
            rem[w] = (K >= lo + 32) ? 0xffffffffu : (K > lo ? ((1u << (K - lo)) - 1u) : 0u);
        }
        u32 kw[4] = {0, 0, 0, 0};
#pragma unroll
        for (int w = 0; w < 4; w++) {
            while (rem[w]) {
                int bit = __ffs(rem[w]) - 1;
                int i = w * 32 + bit;
                kw[w] |= 1u << bit;
                rem[w] &= ~(1u << bit);
                uint4 row = *(const uint4*)&smask[wid][i * 4];
                rem[0] &= ~row.x; rem[1] &= ~row.y;
                rem[2] &= ~row.z; rem[3] &= ~row.w;
            }
        }
        int nkeep = __popc(kw[0]) + __popc(kw[1]) + __popc(kw[2]) + __popc(kw[3]);
        base = atomicAdd(&g_poolCnt[b], nkeep);
        kw0 = kw[0]; kw1 = kw[1]; kw2 = kw[2]; kw3 = kw[3];
    }
    kw0 = __shfl_sync(FULL, kw0, 0);
    kw1 = __shfl_sync(FULL, kw1, 0);
    kw2 = __shfl_sync(FULL, kw2, 0);
    kw3 = __shfl_sync(FULL, kw3, 0);
    base = __shfl_sync(FULL, base, 0);

    int pre1 = __popc(kw0);
    int pre2 = pre1 + __popc(kw1);
    int pre3 = pre2 + __popc(kw2);
#pragma unroll
    for (int r = 0; r < 4; r++) {
        int e = r * 32 + lane;
        u32 kwr = (r == 0) ? kw0 : (r == 1) ? kw1 : (r == 2) ? kw2 : kw3;
        int prer = (r == 0) ? 0 : (r == 1) ? pre1 : (r == 2) ? pre2 : pre3;
        if (e < K && ((kwr >> lane) & 1u)) {
            int rank = prer + __popc(kwr & ((1u << lane) - 1u));
            u64 kk = key[r];
            int a = (int)(~(u32)kk) & 0xFFF;
            int flat = c * KMAX + e;
            u64 det = (kk & 0xFFFFFFFF00000000ULL)
                    | ((u64)(u32)(32767 - flat) << 17)
                    | ((u64)(u32)a << 5);
            int pos = base + rank;
            if (pos < POOLCAP) g_pool[(size_t)b * POOLCAP + pos] = det;
        }
    }
}

// score bucket: monotonic linear map of score (0,1] -> 0..4095
__device__ __forceinline__ int score_bucket(u64 kk) {
    float sc = __uint_as_float((u32)(kk >> 32));
    int d = (int)(sc * 4096.0f);
    return d > 4095 ? 4095 : d;
}

// -------- kernel 3: big-class fallback + 1-pass score-hist top-100 + re-zero ----
__global__ void __launch_bounds__(1024) k_top(float* __restrict__ out) {
    __shared__ int hist[4096];
    __shared__ int segs[256];
    __shared__ u64 sel[128];
    __shared__ int sh_cnt;
    __shared__ u64 sh_prefix;
    __shared__ int sh_rem, sh_total, sh_d;
    __shared__ u64 fkeys[CAP];
    __shared__ float4 fbox[KMAX];
    __shared__ float farea[KMAX];
    __shared__ u32 fmask[KMAX * WMAX];
    __shared__ int fkl[KMAX];
    __shared__ int f_nk, f_base;

    int b = blockIdx.x, tid = threadIdx.x;

    // ---- rare fallback: block-level NMS for this image's m>128 classes ----
    int nbig = g_bigCnt;
    for (int idx = 0; idx < nbig; idx++) {
        int li = g_bigList[idx];
        if (li / CM1 != b) continue;
        int c = li - b * CM1;
        int mm = g_candCnt[li];
        if (mm > CAP) mm = CAP;

        int n = 1; while (n < mm) n <<= 1;
        for (int i = tid; i < n; i += 1024)
            fkeys[i] = (i < mm) ? g_cand[(size_t)li * CAP + i] : 0ULL;
        __syncthreads();
        for (int k = 2; k <= n; k <<= 1)
            for (int j = k >> 1; j > 0; j >>= 1) {
                for (int i = tid; i < n; i += 1024) {
                    int x = i ^ j;
                    if (x > i) {
                        u64 A = fkeys[i], Bv = fkeys[x];
                        bool up = (i & k) == 0;
                        if (up ? (A < Bv) : (A > Bv)) { fkeys[i] = Bv; fkeys[x] = A; }
                    }
                }
                __syncthreads();
            }

        int K = mm < KMAX ? mm : KMAX;
        for (int r = tid; r < K; r += 1024) {
            int a = (int)(~(u32)fkeys[r]);
            float4 bb = g_boxes[b * NA + a];
            fbox[r] = bb;
            farea[r] = fmaxf(bb.z - bb.x, 0.f) * fmaxf(bb.w - bb.y, 0.f);
        }
        __syncthreads();

        int W = (K + 31) >> 5;
        for (int w = tid; w < K * W; w += 1024) {
            int i = w / W, seg = w - i * W;
            u32 bits = 0;
            float4 bi = fbox[i];
            float ai = farea[i];
            int j0 = seg << 5;
            int je = min(j0 + 32, K);
            for (int j = max(j0, i + 1); j < je; j++) {
                float4 bj = fbox[j];
                float iw = fminf(bi.z, bj.z) - fmaxf(bi.x, bj.x);
                float ih = fminf(bi.w, bj.w) - fmaxf(bi.y, bj.y);
                iw = fmaxf(iw, 0.f); ih = fmaxf(ih, 0.f);
                float inter = iw * ih;
                float uni = ai + farea[j] - inter;
                if (inter > 0.4985f * uni)
                    if (__fdiv_rn(inter, fmaxf(uni, 1e-9f)) > 0.5f)
                        bits |= 1u << (j - j0);
            }
            fmask[i * W + seg] = bits;
        }
        __syncthreads();

        if (tid == 0) {
            u32 remv[WMAX] = {0, 0, 0, 0, 0, 0, 0};
            int nkeep = 0;
            for (int i = 0; i < K; i++) {
                if (!((remv[i >> 5] >> (i & 31)) & 1u)) {
                    fkl[nkeep++] = i;
                    for (int w = 0; w < W; w++) remv[w] |= fmask[i * W + w];
                }
            }
            f_nk = nkeep;
            f_base = atomicAdd(&g_poolCnt[b], nkeep);
        }
        __syncthreads();

        int nk = f_nk, bse = f_base;
        for (int sidx = tid; sidx < nk; sidx += 1024) {
            int i = fkl[sidx];
            u64 kk = fkeys[i];
            int a = (int)(~(u32)kk) & 0xFFF;
            int flat = c * KMAX + i;
            u64 det = (kk & 0xFFFFFFFF00000000ULL)
                    | ((u64)(u32)(32767 - flat) << 17)
                    | ((u64)(u32)a << 5);
            int pos = bse + sidx;
            if (pos < POOLCAP) g_pool[(size_t)b * POOLCAP + pos] = det;
        }
        __syncthreads();
    }

    // ---- selection: 1-pass linear-score histogram (fallback: exact u64 radix) ----
    int m = g_poolCnt[b]; if (m > POOLCAP) m = POOLCAP;
    const u64* pool = g_pool + (size_t)b * POOLCAP;

    u64 kth = 0;        // used by fallback path
    int dstar = -1;     // used by fast path (bucket threshold)
    if (m > 100) {
        // fast path: histogram over score buckets
        for (int d = tid; d < 4096; d += 1024) hist[d] = 0;
        __syncthreads();
        for (int i = tid; i < m; i += 1024)
            atomicAdd(&hist[score_bucket(pool[i])], 1);
        __syncthreads();
        if (tid < 256) {
            int s = 0;
#pragma unroll
            for (int q = 0; q < 16; q++) s += hist[tid * 16 + q];
            segs[tid] = s;
        }
        __syncthreads();
        if (tid < 32) {
            int sv[8]; int lsum = 0;
#pragma unroll
            for (int q = 0; q < 8; q++) { sv[q] = segs[tid * 8 + q]; lsum += sv[q]; }
            int acc = lsum;
#pragma unroll
            for (int off = 1; off < 32; off <<= 1) {
                int v = __shfl_down_sync(FULL, acc, off);
                if (tid + off < 32) acc += v;
            }
            int run = acc - lsum;
#pragma unroll
            for (int q = 7; q >= 0; q--) { run += sv[q]; segs[tid * 8 + q] = run; }
        }
        __syncthreads();
        if (tid < 256) {
            int run = (tid < 255) ? segs[tid + 1] : 0;
#pragma unroll
            for (int q = 15; q >= 0; q--) {
                int d = tid * 16 + q;
                int ge = run + hist[d];
                if (ge >= 100 && run < 100) {
                    sh_d = d;
                    sh_total = ge;
                }
                run = ge;
            }
        }
        __syncthreads();
        if (sh_total <= 128) {
            dstar = sh_d;                       // 1-pass success (typical)
        } else {
            // exact 4-pass u64 radix fallback (rare: >28 keys in one bucket at rank 100)
            u64 prefix = 0; int rem = 100;
            for (int pass = 0; pass < 4; pass++) {
                int shift = 52 - 12 * pass;
                for (int d = tid; d < 4096; d += 1024) hist[d] = 0;
                __syncthreads();
                for (int i = tid; i < m; i += 1024) {
                    u64 kk = pool[i];
                    if (pass == 0 || (kk >> (shift + 12)) == prefix)
                        atomicAdd(&hist[(int)((kk >> shift) & 0xFFF)], 1);
                }
                __syncthreads();
                if (tid < 256) {
                    int s = 0;
#pragma unroll
                    for (int q = 0; q < 16; q++) s += hist[tid * 16 + q];
                    segs[tid] = s;
                }
                __syncthreads();
                if (tid < 32) {
                    int sv[8]; int lsum = 0;
#pragma unroll
                    for (int q = 0; q < 8; q++) { sv[q] = segs[tid * 8 + q]; lsum += sv[q]; }
                    int acc = lsum;
#pragma unroll
                    for (int off = 1; off < 32; off <<= 1) {
                        int v = __shfl_down_sync(FULL, acc, off);
                        if (tid + off < 32) acc += v;
                    }
                    int run = acc - lsum;
#pragma unroll
                    for (int q = 7; q >= 0; q--) { run += sv[q]; segs[tid * 8 + q] = run; }
                }
                __syncthreads();
                if (tid < 256) {
                    int run = (tid < 255) ? segs[tid + 1] : 0;
#pragma unroll
                    for (int q = 15; q >= 0; q--) {
                        int d = tid * 16 + q;
                        int ge = run + hist[d];
                        if (ge >= rem && run < rem) {
                            sh_prefix = (prefix << 12) | (u64)d;
                            sh_rem = rem - run;
                            sh_total = (100 - rem) + ge;
                        }
                        run = ge;
                    }
                }
                __syncthreads();
                prefix = sh_prefix; rem = sh_rem;
                int total = sh_total;
                __syncthreads();
                kth = prefix << shift;
                if (total <= 128) break;
            }
        }
    }

    if (tid == 0) sh_cnt = 0;
    __syncthreads();
    for (int i = tid; i < m; i += 1024) {
        u64 kk = pool[i];
        bool take = (dstar >= 0) ? (score_bucket(kk) >= dstar) : (kk >= kth);
        if (take) {
            int p = atomicAdd(&sh_cnt, 1);
            if (p < 128) sel[p] = kk;
        }
    }
    __syncthreads();
    int cnt = sh_cnt; if (cnt > 128) cnt = 128;
    int nsel = cnt < 100 ? cnt : 100;
    if (tid < 128 && tid >= cnt) sel[tid] = 0;
    __syncthreads();

    if (tid < 32) {
        u64 kk[4];
#pragma unroll
        for (int r = 0; r < 4; r++) kk[r] = sel[r * 32 + tid];
        warp_bitonic_desc<4>(kk, tid);
#pragma unroll
        for (int r = 0; r < 4; r++) sel[r * 32 + tid] = kk[r];
    }
    __syncthreads();

    for (int r = tid; r < 100; r += 1024) {
        float o0 = 0, o1 = 0, o2 = 0, o3 = 0, o4 = 0, o5 = 0;
        if (r < nsel) {
            u64 kk = sel[r];
            float sc = __uint_as_float((u32)(kk >> 32));
            int flat = 32767 - (int)((kk >> 17) & 0x7FFF);
            int cls = flat / 200 + 1;
            int a = (int)((kk >> 5) & 0xFFF);
            float4 bb = g_boxes[b * NA + a];
            o0 = bb.x; o1 = bb.y; o2 = bb.z; o3 = bb.w; o4 = sc; o5 = (float)cls;
        }
        float* op = out + ((size_t)b * 100 + r) * 6;
        op[0] = o0; op[1] = o1; op[2] = o2; op[3] = o3; op[4] = o4; op[5] = o5;
    }

    // ---- re-zero this image's counters for the next replay (after all use) ----
    for (int i = tid; i < CM1; i += 1024) g_candCnt[b * CM1 + i] = 0;
    __syncthreads();
    if (tid == 0) {
        g_poolCnt[b] = 0;
        __threadfence();
        int t = atomicAdd(&g_doneCnt, 1);
        if (t == BATCH - 1) { g_bigCnt = 0; g_doneCnt = 0; }
    }
}

// -------- launch --------
extern "C" void kernel_launch(void* const* d_in, const int* in_sizes, int n_in,
                              void* d_out, int out_size) {
    const float* logits = nullptr;
    const float* boxreg = nullptr;
    const float* priors = nullptr;
    for (int i = 0; i < n_in; i++) {
        if (in_sizes[i] == BATCH * NA * NC) logits = (const float*)d_in[i];
        else if (in_sizes[i] == BATCH * NA * 4) boxreg = (const float*)d_in[i];
        else if (in_sizes[i] == NA * 4) priors = (const float*)d_in[i];
    }
    float* out = (float*)d_out;

    k_cand<<<CGRID, 256>>>(logits, boxreg, priors);
    k_nms_warp<<<(BATCH * CM1 + 3) / 4, 128>>>();
    k_top<<<BATCH, 1024>>>(out);
}

// round 17
// speedup vs baseline: 1.2116x; 1.0036x over previous
#include <cuda_runtime.h>
#include <stdint.h>

#define BATCH   64
#define NA      3234
#define NC      91
#define CM1     90
#define CAP     512
#define KMAX    200
#define WMAX    7
#define POOLCAP 16384
#define NWORK   (BATCH * NA / 2)      // dual-anchor work items
#define CGRID   1184                  // 148 SMs x 8 resident blocks

typedef unsigned long long u64;
typedef unsigned int u32;
#define FULL 0xffffffffu

// -------- scratch (static __device__ — zero-init at load; re-zeroed by k_top) ----
__device__ float4 g_boxes[BATCH * NA];
__device__ u64    g_cand[(size_t)BATCH * CM1 * CAP];
__device__ int    g_candCnt[BATCH * CM1];
__device__ u64    g_pool[(size_t)BATCH * POOLCAP];
__device__ int    g_poolCnt[BATCH];
__device__ int    g_bigCnt;
__device__ int    g_bigList[BATCH * CM1];
__device__ int    g_doneCnt;

// ~1-ulp exp, FMA-only (immune to fast-math substitution).
__device__ __forceinline__ float exp_acc(float x) {
    float k = rintf(x * 1.44269504088896340736f);
    float r = fmaf(k, -0.693359375f, x);
    r = fmaf(k, 2.12194440054690582762e-4f, r);
    float p = 1.98412698412698413e-4f;
    p = fmaf(p, r, 1.38888888888888889e-3f);
    p = fmaf(p, r, 8.33333333333333333e-3f);
    p = fmaf(p, r, 4.16666666666666667e-2f);
    p = fmaf(p, r, 1.66666666666666667e-1f);
    p = fmaf(p, r, 0.5f);
    p = fmaf(p, r, 1.0f);
    p = fmaf(p, r, 1.0f);
    int ki = (int)k;
    ki = max(-126, min(126, ki));
    return p * __int_as_float((ki + 127) << 23);
}

__device__ __forceinline__ u32 f2ord(float x) {
    u32 u = __float_as_uint(x);
    return (u & 0x80000000u) ? ~u : (u | 0x80000000u);
}
__device__ __forceinline__ float ord2f(u32 k) {
    u32 u = (k & 0x80000000u) ? (k ^ 0x80000000u) : ~k;
    return __uint_as_float(u);
}

// ---- packed f32x2 helpers (sm_103a; only add/mul/fma exist in this PTX) ----
#define MUL2(d, a, b)    asm("mul.rn.f32x2 %0, %1, %2;" : "=l"(d) : "l"(a), "l"(b))
#define ADD2(d, a, b)    asm("add.rn.f32x2 %0, %1, %2;" : "=l"(d) : "l"(a), "l"(b))
#define FMA2(d, a, b, c) asm("fma.rn.f32x2 %0, %1, %2, %3;" : "=l"(d) : "l"(a), "l"(b), "l"(c))

__device__ __forceinline__ u64 pk2(float lo, float hi) {
    u64 r; asm("mov.b64 %0, {%1, %2};" : "=l"(r) : "f"(lo), "f"(hi)); return r;
}
__device__ __forceinline__ void upk2(u64 v, float& lo, float& hi) {
    asm("mov.b64 {%0, %1}, %2;" : "=f"(lo), "=f"(hi) : "l"(v));
}
__device__ __forceinline__ u64 dupc(float f) {
    u32 u = __float_as_uint(f);
    return ((u64)u << 32) | (u64)u;
}

// packed dual exp — per-half bit-identical to exp_acc for x in [-80, 0]
// (callers clamp inputs at -80, so k >= -116 and the scale never underflows;
//  the int clamps are therefore dropped). rint via magic add (RN ties-even).
__device__ __forceinline__ u64 exp_acc2(u64 x2) {
    u64 t, km, k2, r, p;
    MUL2(t, x2, dupc(1.44269504088896340736f));
    ADD2(km, t, dupc(12582912.0f));            // 1.5*2^23: km = magic + rint(t)
    ADD2(k2, km, dupc(-12582912.0f));          // k = rint(t), exact
    FMA2(r, k2, dupc(-0.693359375f), x2);
    FMA2(r, k2, dupc(2.12194440054690582762e-4f), r);
    p = dupc(1.98412698412698413e-4f);
    FMA2(p, p, r, dupc(1.38888888888888889e-3f));
    FMA2(p, p, r, dupc(8.33333333333333333e-3f));
    FMA2(p, p, r, dupc(4.16666666666666667e-2f));
    FMA2(p, p, r, dupc(1.66666666666666667e-1f));
    FMA2(p, p, r, dupc(0.5f));
    FMA2(p, p, r, dupc(1.0f));
    FMA2(p, p, r, dupc(1.0f));
    int kia = (int)((u32)km - 0x4B400000u);    // integer k, low half (>= -116)
    int kib = (int)((u32)(km >> 32) - 0x4B400000u);
    u64 sc = ((u64)((u32)(kib + 127) << 23) << 32) | (u32)((kia + 127) << 23);
    u64 out;
    MUL2(out, p, sc);
    return out;
}

// warp-collective descending bitonic sort, R u64 keys per lane (N = 32*R).
template <int R>
__device__ __forceinline__ void warp_bitonic_desc(u64 key[4], int lane) {
    const int N = R * 32;
#pragma unroll
    for (int k = 2; k <= N; k <<= 1) {
#pragma unroll
        for (int j = k >> 1; j > 0; j >>= 1) {
            if (j >= 32) {
                int rj = j >> 5;
#pragma unroll
                for (int r = 0; r < R; r++) {
                    if ((r & rj) == 0) {
                        int rp = r | rj;
                        int e = r * 32 + lane;
                        bool desc = ((e & k) == 0);
                        u64 A = key[r], Bv = key[rp];
                        if (desc ? (A < Bv) : (A > Bv)) { key[r] = Bv; key[rp] = A; }
                    }
                }
            } else {
#pragma unroll
                for (int r = 0; r < R; r++) {
                    u64 other = __shfl_xor_sync(FULL, key[r], j);
                    int e = r * 32 + lane;
                    bool desc = ((e & k) == 0);
                    bool lower = ((lane & j) == 0);
                    if (desc == lower) key[r] = (key[r] > other) ? key[r] : other;
                    else               key[r] = (key[r] < other) ? key[r] : other;
                }
            }
        }
    }
}

// -------- kernel 1: persistent fused decode + dual-anchor softmax + filter ------
__device__ __forceinline__ void push_cand2(float e, int cm1, bool cvalid,
                                           int b, int a, float s, float pre) {
    if (cvalid && e > pre) {
        float p = __fdiv_rn(e, s);
        if (p > 0.05f) {
            int li = b * CM1 + cm1;
            int pos = atomicAdd(&g_candCnt[li], 1);
            if (pos < CAP)
                g_cand[(size_t)li * CAP + pos] =
                    ((u64)__float_as_uint(p) << 32) | (u32)(~(u32)a);
        }
    }
}

__global__ void __launch_bounds__(256) k_cand(const float* __restrict__ logits,
                                              const float* __restrict__ box_reg,
                                              const float* __restrict__ priors) {
    // decode: grid-stride, one thread per (b,a)
    for (int di = blockIdx.x * 256 + threadIdx.x; di < BATCH * NA;
         di += gridDim.x * 256) {
        int da = di % NA;
        float4 loc = ((const float4*)box_reg)[di];
        float4 pr  = ((const float4*)priors)[da];
        float pw = pr.z - pr.x, ph = pr.w - pr.y;
        float cx = pr.x + 0.5f * pw, cy = pr.y + 0.5f * ph;
        float x = loc.x * 0.1f * pw + cx;
        float y = loc.y * 0.1f * ph + cy;
        float w = exp_acc(loc.z * 0.2f) * pw;
        float h = exp_acc(loc.w * 0.2f) * ph;
        g_boxes[di] = make_float4(x - w * 0.5f, y - h * 0.5f, x + w * 0.5f, y + h * 0.5f);
    }

    // softmax+filter: grid-stride over dual-anchor work items, one per warp
    int lane = threadIdx.x & 31;
    int wid = threadIdx.x >> 5;
    for (int gw = blockIdx.x * 8 + wid; gw < NWORK; gw += gridDim.x * 8) {
        int idx0 = gw * 2;
        int idx1 = idx0 + 1;
        int b0 = idx0 / NA, a0 = idx0 - b0 * NA;
        int b1 = b0, a1 = a0 + 1;
        if (a1 == NA) { b1 = b0 + 1; a1 = 0; }
        const float* LA = logits + (size_t)idx0 * NC;
        const float* LB = logits + (size_t)idx1 * NC;
        bool t2 = lane < NC - 64;

        float al0 = LA[lane];
        float al1 = LA[lane + 32];
        float al2 = t2 ? LA[lane + 64] : -1e30f;
        float bl0 = LB[lane];
        float bl1 = LB[lane + 32];
        float bl2 = t2 ? LB[lane + 64] : -1e30f;

        // exact max: fmaxf chain per anchor, single ord-map before redux
        float pa = fmaxf(fmaxf(al0, al1), al2);
        float pb = fmaxf(fmaxf(bl0, bl1), bl2);
        float mxa = ord2f(__reduce_max_sync(FULL, f2ord(pa)));
        float mxb = ord2f(__reduce_max_sync(FULL, f2ord(pb)));

        // packed exps, inputs clamped at -80 (decision- and sum-identical;
        // guarantees no scale underflow so exp_acc2 needs no int clamps)
        u64 x0 = pk2(fmaxf(al0 - mxa, -80.f), fmaxf(bl0 - mxb, -80.f));
        u64 x1 = pk2(fmaxf(al1 - mxa, -80.f), fmaxf(bl1 - mxb, -80.f));
        u64 xv2 = pk2(fmaxf(al2 - mxa, -80.f), fmaxf(bl2 - mxb, -80.f));
        u64 e0p = exp_acc2(x0);
        u64 e1p = exp_acc2(x1);
        u64 e2p = t2 ? exp_acc2(xv2) : 0ULL;

        u64 pk;
        ADD2(pk, e0p, e1p);
        ADD2(pk, pk, e2p);
#pragma unroll
        for (int o = 16; o; o >>= 1) {
            u64 other = __shfl_xor_sync(FULL, pk, o);
            ADD2(pk, pk, other);
        }
        float sa, sb;
        upk2(pk, sa, sb);

        float ea0, eb0, ea1, eb1, ea2, eb2;
        upk2(e0p, ea0, eb0);
        upk2(e1p, ea1, eb1);
        upk2(e2p, ea2, eb2);

        float prea = 0.0495f * sa;
        float preb = 0.0495f * sb;
        bool l0v = lane > 0;
        push_cand2(ea0, lane - 1,  l0v,  b0, a0, sa, prea);
        push_cand2(eb0, lane - 1,  l0v,  b1, a1, sb, preb);
        push_cand2(ea1, lane + 31, true, b0, a0, sa, prea);
        push_cand2(eb1, lane + 31, true, b1, a1, sb, preb);
        push_cand2(ea2, lane + 63, true, b0, a0, sa, prea);
        push_cand2(eb2, lane + 63, true, b1, a1, sb, preb);
    }
}

// -------- kernel 2: warp-per-class NMS (shared masks, lane-0 scan) --------
__global__ void __launch_bounds__(128) k_nms_warp() {
    __shared__ float4 sbox[4][128];
    __shared__ float  sarea[4][128];
    __shared__ u32    smask[4][128 * 4];

    int wid = threadIdx.x >> 5;
    int lane = threadIdx.x & 31;
    int li = blockIdx.x * 4 + wid;
    if (li >= BATCH * CM1) return;
    int b = li / CM1;
    int c = li - b * CM1;

    int m = g_candCnt[li];
    if (m == 0) return;
    if (m > 128) {                         // rare fallback, handled in k_top
        if (lane == 0) {
            int p = atomicAdd(&g_bigCnt, 1);
            g_bigList[p] = li;
        }
        return;
    }

    u64 key[4];
#pragma unroll
    for (int r = 0; r < 4; r++) {
        int e = r * 32 + lane;
        key[r] = (e < m) ? g_cand[(size_t)li * CAP + e] : 0ULL;
    }

    if (m <= 64) warp_bitonic_desc<2>(key, lane);   // 21 stages, 2 keys/lane
    else         warp_bitonic_desc<4>(key, lane);   // 28 stages, 4 keys/lane

    int K = m;   // <= 128 <= KMAX

#pragma unroll
    for (int r = 0; r < 4; r++) {
        int e = r * 32 + lane;
        if (e < K) {
            int a = (int)(~(u32)key[r]);
            float4 bb = g_boxes[b * NA + a];
            sbox[wid][e] = bb;
            sarea[wid][e] = fmaxf(bb.z - bb.x, 0.f) * fmaxf(bb.w - bb.y, 0.f);
        }
    }
    __syncwarp();

    // suppression rows: load-balanced row map {lane, 63-lane, 64+lane, 127-lane}
    int lastseg = (K - 1) >> 5;
#pragma unroll
    for (int rr = 0; rr < 4; rr++) {
        int i;
        if (rr == 0)      i = lane;
        else if (rr == 1) i = 63 - lane;
        else if (rr == 2) i = 64 + lane;
        else              i = 127 - lane;
        if (i < K) {
            float4 bi = sbox[wid][i];
            float ai = sarea[wid][i];
#pragma unroll
            for (int seg = 0; seg < 4; seg++) {
                u32 bits = 0;
                if (seg <= lastseg) {
                    int j0 = seg << 5; if (j0 < i + 1) j0 = i + 1;
                    int je = (seg << 5) + 32; if (je > K) je = K;
                    for (int j = j0; j < je; j++) {
                        float4 bj = sbox[wid][j];
                        float iw = fminf(bi.z, bj.z) - fmaxf(bi.x, bj.x);
                        float ih = fminf(bi.w, bj.w) - fmaxf(bi.y, bj.y);
                        iw = fmaxf(iw, 0.f); ih = fmaxf(ih, 0.f);
                        float inter = iw * ih;
                        float sum = ai + sarea[wid][j];
                        if (inter > 0.332f * sum) {      // superset prefilter
                            float uni = sum - inter;
                            if (__fdiv_rn(inter, fmaxf(uni, 1e-9f)) > 0.5f)
                                bits |= 1u << (j & 31);
                        }
                    }
                }
                smask[wid][i * 4 + seg] = bits;
            }
        }
    }
    __syncwarp();

    u32 kw0 = 0, kw1 = 0, kw2 = 0, kw3 = 0;
    int base = 0;
    if (lane == 0) {
        u32 rem[4];
#pragma unroll
        for (int w = 0; w < 4; w++) {
            int lo = w * 32;
            rem[w] = (K >= lo + 32) ? 0xffffffffu : (K > lo ? ((1u << (K - lo)) - 1u) : 0u);
        }
        u32 kw[4] = {0, 0, 0, 0};
#pragma unroll
        for (int w = 0; w < 4; w++) {
            while (rem[w]) {
                int bit = __ffs(rem[w]) - 1;
                int i = w * 32 + bit;
                kw[w] |= 1u << bit;
                rem[w] &= ~(1u << bit);
                uint4 row = *(const uint4*)&smask[wid][i * 4];
                rem[0] &= ~row.x; rem[1] &= ~row.y;
                rem[2] &= ~row.z; rem[3] &= ~row.w;
            }
        }
        int nkeep = __popc(kw[0]) + __popc(kw[1]) + __popc(kw[2]) + __popc(kw[3]);
        base = atomicAdd(&g_poolCnt[b], nkeep);
        kw0 = kw[0]; kw1 = kw[1]; kw2 = kw[2]; kw3 = kw[3];
    }
    kw0 = __shfl_sync(FULL, kw0, 0);
    kw1 = __shfl_sync(FULL, kw1, 0);
    kw2 = __shfl_sync(FULL, kw2, 0);
    kw3 = __shfl_sync(FULL, kw3, 0);
    base = __shfl_sync(FULL, base, 0);

    int pre1 = __popc(kw0);
    int pre2 = pre1 + __popc(kw1);
    int pre3 = pre2 + __popc(kw2);
#pragma unroll
    for (int r = 0; r < 4; r++) {
        int e = r * 32 + lane;
        u32 kwr = (r == 0) ? kw0 : (r == 1) ? kw1 : (r == 2) ? kw2 : kw3;
        int prer = (r == 0) ? 0 : (r == 1) ? pre1 : (r == 2) ? pre2 : pre3;
        if (e < K && ((kwr >> lane) & 1u)) {
            int rank = prer + __popc(kwr & ((1u << lane) - 1u));
            u64 kk = key[r];
            int a = (int)(~(u32)kk) & 0xFFF;
            int flat = c * KMAX + e;
            u64 det = (kk & 0xFFFFFFFF00000000ULL)
                    | ((u64)(u32)(32767 - flat) << 17)
                    | ((u64)(u32)a << 5);
            int pos = base + rank;
            if (pos < POOLCAP) g_pool[(size_t)b * POOLCAP + pos] = det;
        }
    }
}

// score bucket: monotonic linear map of score (0,1] -> 0..4095
__device__ __forceinline__ int score_bucket(u64 kk) {
    float sc = __uint_as_float((u32)(kk >> 32));
    int d = (int)(sc * 4096.0f);
    return d > 4095 ? 4095 : d;
}

// -------- kernel 3: big-class fallback + 1-pass score-hist top-100 + re-zero ----
__global__ void __launch_bounds__(1024) k_top(float* __restrict__ out) {
    __shared__ int hist[4096];
    __shared__ int segs[256];
    __shared__ u64 sel[128];
    __shared__ int sh_cnt;
    __shared__ u64 sh_prefix;
    __shared__ int sh_rem, sh_total, sh_d;
    __shared__ u64 fkeys[CAP];
    __shared__ float4 fbox[KMAX];
    __shared__ float farea[KMAX];
    __shared__ u32 fmask[KMAX * WMAX];
    __shared__ int fkl[KMAX];
    __shared__ int f_nk, f_base;

    int b = blockIdx.x, tid = threadIdx.x;

    // ---- rare fallback: block-level NMS for this image's m>128 classes ----
    int nbig = g_bigCnt;
    for (int idx = 0; idx < nbig; idx++) {
        int li = g_bigList[idx];
        if (li / CM1 != b) continue;
        int c = li - b * CM1;
        int mm = g_candCnt[li];
        if (mm > CAP) mm = CAP;

        int n = 1; while (n < mm) n <<= 1;
        for (int i = tid; i < n; i += 1024)
            fkeys[i] = (i < mm) ? g_cand[(size_t)li * CAP + i] : 0ULL;
        __syncthreads();
        for (int k = 2; k <= n; k <<= 1)
            for (int j = k >> 1; j > 0; j >>= 1) {
                for (int i = tid; i < n; i += 1024) {
                    int x = i ^ j;
                    if (x > i) {
                        u64 A = fkeys[i], Bv = fkeys[x];
                        bool up = (i & k) == 0;
                        if (up ? (A < Bv) : (A > Bv)) { fkeys[i] = Bv; fkeys[x] = A; }
                    }
                }
                __syncthreads();
            }

        int K = mm < KMAX ? mm : KMAX;
        for (int r = tid; r < K; r += 1024) {
            int a = (int)(~(u32)fkeys[r]);
            float4 bb = g_boxes[b * NA + a];
            fbox[r] = bb;
            farea[r] = fmaxf(bb.z - bb.x, 0.f) * fmaxf(bb.w - bb.y, 0.f);
        }
        __syncthreads();

        int W = (K + 31) >> 5;
        for (int w = tid; w < K * W; w += 1024) {
            int i = w / W, seg = w - i * W;
            u32 bits = 0;
            float4 bi = fbox[i];
            float ai = farea[i];
            int j0 = seg << 5;
            int je = min(j0 + 32, K);
            for (int j = max(j0, i + 1); j < je; j++) {
                float4 bj = fbox[j];
                float iw = fminf(bi.z, bj.z) - fmaxf(bi.x, bj.x);
                float ih = fminf(bi.w, bj.w) - fmaxf(bi.y, bj.y);
                iw = fmaxf(iw, 0.f); ih = fmaxf(ih, 0.f);
                float inter = iw * ih;
                float uni = ai + farea[j] - inter;
                if (inter > 0.4985f * uni)
                    if (__fdiv_rn(inter, fmaxf(uni, 1e-9f)) > 0.5f)
                        bits |= 1u << (j - j0);
            }
            fmask[i * W + seg] = bits;
        }
        __syncthreads();

        if (tid == 0) {
            u32 remv[WMAX] = {0, 0, 0, 0, 0, 0, 0};
            int nkeep = 0;
            for (int i = 0; i < K; i++) {
                if (!((remv[i >> 5] >> (i & 31)) & 1u)) {
                    fkl[nkeep++] = i;
                    for (int w = 0; w < W; w++) remv[w] |= fmask[i * W + w];
                }
            }
            f_nk = nkeep;
            f_base = atomicAdd(&g_poolCnt[b], nkeep);
        }
        __syncthreads();

        int nk = f_nk, bse = f_base;
        for (int sidx = tid; sidx < nk; sidx += 1024) {
            int i = fkl[sidx];
            u64 kk = fkeys[i];
            int a = (int)(~(u32)kk) & 0xFFF;
            int flat = c * KMAX + i;
            u64 det = (kk & 0xFFFFFFFF00000000ULL)
                    | ((u64)(u32)(32767 - flat) << 17)
                    | ((u64)(u32)a << 5);
            int pos = bse + sidx;
            if (pos < POOLCAP) g_pool[(size_t)b * POOLCAP + pos] = det;
        }
        __syncthreads();
    }

    // ---- selection: 1-pass linear-score histogram (fallback: exact u64 radix) ----
    int m = g_poolCnt[b]; if (m > POOLCAP) m = POOLCAP;
    const u64* pool = g_pool + (size_t)b * POOLCAP;

    u64 kth = 0;        // used by fallback path
    int dstar = -1;     // used by fast path (bucket threshold)
    if (m > 100) {
        // fast path: histogram over score buckets
        for (int d = tid; d < 4096; d += 1024) hist[d] = 0;
        __syncthreads();
        for (int i = tid; i < m; i += 1024)
            atomicAdd(&hist[score_bucket(pool[i])], 1);
        __syncthreads();
        if (tid < 256) {
            int s = 0;
#pragma unroll
            for (int q = 0; q < 16; q++) s += hist[tid * 16 + q];
            segs[tid] = s;
        }
        __syncthreads();
        if (tid < 32) {
            int sv[8]; int lsum = 0;
#pragma unroll
            for (int q = 0; q < 8; q++) { sv[q] = segs[tid * 8 + q]; lsum += sv[q]; }
            int acc = lsum;
#pragma unroll
            for (int off = 1; off < 32; off <<= 1) {
                int v = __shfl_down_sync(FULL, acc, off);
                if (tid + off < 32) acc += v;
            }
            int run = acc - lsum;
#pragma unroll
            for (int q = 7; q >= 0; q--) { run += sv[q]; segs[tid * 8 + q] = run; }
        }
        __syncthreads();
        if (tid < 256) {
            int run = (tid < 255) ? segs[tid + 1] : 0;
#pragma unroll
            for (int q = 15; q >= 0; q--) {
                int d = tid * 16 + q;
                int ge = run + hist[d];
                if (ge >= 100 && run < 100) {
                    sh_d = d;
                    sh_total = ge;
                }
                run = ge;
            }
        }
        __syncthreads();
        if (sh_total <= 128) {
            dstar = sh_d;                       // 1-pass success (typical)
        } else {
            // exact 4-pass u64 radix fallback (rare: >28 keys in one bucket at rank 100)
            u64 prefix = 0; int rem = 100;
            for (int pass = 0; pass < 4; pass++) {
                int shift = 52 - 12 * pass;
                for (int d = tid; d < 4096; d += 1024) hist[d] = 0;
                __syncthreads();
                for (int i = tid; i < m; i += 1024) {
                    u64 kk = pool[i];
                    if (pass == 0 || (kk >> (shift + 12)) == prefix)
                        atomicAdd(&hist[(int)((kk >> shift) & 0xFFF)], 1);
                }
                __syncthreads();
                if (tid < 256) {
                    int s = 0;
#pragma unroll
                    for (int q = 0; q < 16; q++) s += hist[tid * 16 + q];
                    segs[tid] = s;
                }
                __syncthreads();
                if (tid < 32) {
                    int sv[8]; int lsum = 0;
#pragma unroll
                    for (int q = 0; q < 8; q++) { sv[q] = segs[tid * 8 + q]; lsum += sv[q]; }
                    int acc = lsum;
#pragma unroll
                    for (int off = 1; off < 32; off <<= 1) {
                        int v = __shfl_down_sync(FULL, acc, off);
                        if (tid + off < 32) acc += v;
                    }
                    int run = acc - lsum;
#pragma unroll
                    for (int q = 7; q >= 0; q--) { run += sv[q]; segs[tid * 8 + q] = run; }
                }
                __syncthreads();
                if (tid < 256) {
                    int run = (tid < 255) ? segs[tid + 1] : 0;
#pragma unroll
                    for (int q = 15; q >= 0; q--) {
                        int d = tid * 16 + q;
                        int ge = run + hist[d];
                        if (ge >= rem && run < rem) {
                            sh_prefix = (prefix << 12) | (u64)d;
                            sh_rem = rem - run;
                            sh_total = (100 - rem) + ge;
                        }
                        run = ge;
                    }
                }
                __syncthreads();
                prefix = sh_prefix; rem = sh_rem;
                int total = sh_total;
                __syncthreads();
                kth = prefix << shift;
                if (total <= 128) break;
            }
        }
    }

    if (tid == 0) sh_cnt = 0;
    __syncthreads();
    for (int i = tid; i < m; i += 1024) {
        u64 kk = pool[i];
        bool take = (dstar >= 0) ? (score_bucket(kk) >= dstar) : (kk >= kth);
        if (take) {
            int p = atomicAdd(&sh_cnt, 1);
            if (p < 128) sel[p] = kk;
        }
    }
    __syncthreads();
    int cnt = sh_cnt; if (cnt > 128) cnt = 128;
    int nsel = cnt < 100 ? cnt : 100;
    if (tid < 128 && tid >= cnt) sel[tid] = 0;
    __syncthreads();

    if (tid < 32) {
        u64 kk[4];
#pragma unroll
        for (int r = 0; r < 4; r++) kk[r] = sel[r * 32 + tid];
        warp_bitonic_desc<4>(kk, tid);
#pragma unroll
        for (int r = 0; r < 4; r++) sel[r * 32 + tid] = kk[r];
    }
    __syncthreads();

    for (int r = tid; r < 100; r += 1024) {
        float o0 = 0, o1 = 0, o2 = 0, o3 = 0, o4 = 0, o5 = 0;
        if (r < nsel) {
            u64 kk = sel[r];
            float sc = __uint_as_float((u32)(kk >> 32));
            int flat = 32767 - (int)((kk >> 17) & 0x7FFF);
            int cls = flat / 200 + 1;
            int a = (int)((kk >> 5) & 0xFFF);
            float4 bb = g_boxes[b * NA + a];
            o0 = bb.x; o1 = bb.y; o2 = bb.z; o3 = bb.w; o4 = sc; o5 = (float)cls;
        }
        float* op = out + ((size_t)b * 100 + r) * 6;
        op[0] = o0; op[1] = o1; op[2] = o2; op[3] = o3; op[4] = o4; op[5] = o5;
    }

    // ---- re-zero this image's counters for the next replay (after all use) ----
    for (int i = tid; i < CM1; i += 1024) g_candCnt[b * CM1 + i] = 0;
    __syncthreads();
    if (tid == 0) {
        g_poolCnt[b] = 0;
        __threadfence();
        int t = atomicAdd(&g_doneCnt, 1);
        if (t == BATCH - 1) { g_bigCnt = 0; g_doneCnt = 0; }
    }
}

// -------- launch --------
extern "C" void kernel_launch(void* const* d_in, const int* in_sizes, int n_in,
                              void* d_out, int out_size) {
    const float* logits = nullptr;
    const float* boxreg = nullptr;
    const float* priors = nullptr;
    for (int i = 0; i < n_in; i++) {
        if (in_sizes[i] == BATCH * NA * NC) logits = (const float*)d_in[i];
        else if (in_sizes[i] == BATCH * NA * 4) boxreg = (const float*)d_in[i];
        else if (in_sizes[i] == NA * 4) priors = (const float*)d_in[i];
    }
    float* out = (float*)d_out;

    k_cand<<<CGRID, 256>>>(logits, boxreg, priors);
    k_nms_warp<<<(BATCH * CM1 + 3) / 4, 128>>>();
    k_top<<<BATCH, 1024>>>(out);
}